// round 9
// baseline (speedup 1.0000x reference)
#include <cuda_runtime.h>
#include <cuda_bf16.h>
#include <math.h>
#include <stdint.h>

// Shapes (fixed for this problem)
#define Bb   8
#define Ll   512
#define Mm   512
#define Hh   8
#define DKk  128
#define DVv  128
#define Ss   512
#define DMm  1024
#define WREC 1024
#define WTOT 1536    // recent 1024 + cache 512

#define INVTAU 0.08838834764831845f   // 1/sqrt(128)

// ---------------- scratch (device globals; no allocation allowed) ------------
__device__ float g_xt  [Bb*Ll*DMm];
__device__ float g_qraw[Bb*Ll*Hh*DKk];
__device__ float g_kvg [Bb*Ll*3072];
__device__ float g_kn  [Bb*Hh*Ll*DKk];
__device__ float g_g   [Bb*Ll*Hh*DVv];
__device__ float g_qu  [64*Ll*DKk];          // q + x_u  (b,h,l,d)
__device__ float g_qv  [64*Ll*DKk];          // q + x_v
__device__ float g_vals[64*WTOT*DVv];        // [xl_v; v; agg_upper]
__device__ float g_S1  [(size_t)64*Ll*WTOT]; // scores -> probs
__device__ float g_S2  [(size_t)64*Ll*WREC]; // BD term
__device__ float g_wvg [Bb*Ll*Hh*DVv];
__device__ int   g_z   [Bb*Hh*Ll];

// ---------------- helpers ----------------------------------------------------
__device__ __forceinline__ float to_tf32(float x) {
    uint32_t u;
    asm("cvt.rna.tf32.f32 %0, %1;" : "=r"(u) : "f"(x));
    return __uint_as_float(u);
}

__device__ __forceinline__ void mma_tf32(float* c, const uint32_t* a, const uint32_t* b) {
    asm volatile(
        "mma.sync.aligned.m16n8k8.row.col.f32.tf32.tf32.f32 "
        "{%0,%1,%2,%3}, {%4,%5,%6,%7}, {%8,%9}, {%0,%1,%2,%3};"
        : "+f"(c[0]), "+f"(c[1]), "+f"(c[2]), "+f"(c[3])
        : "r"(a[0]), "r"(a[1]), "r"(a[2]), "r"(a[3]), "r"(b[0]), "r"(b[1]));
}

__device__ __forceinline__ void mma_bf16(float* c, const uint32_t* a, const uint32_t* b) {
    asm volatile(
        "mma.sync.aligned.m16n8k16.row.col.f32.bf16.bf16.f32 "
        "{%0,%1,%2,%3}, {%4,%5,%6,%7}, {%8,%9}, {%0,%1,%2,%3};"
        : "+f"(c[0]), "+f"(c[1]), "+f"(c[2]), "+f"(c[3])
        : "r"(a[0]), "r"(a[1]), "r"(a[2]), "r"(a[3]), "r"(b[0]), "r"(b[1]));
}

// split two floats into packed bf16x2 hi and lo words (k-pair: x->low, y->high)
__device__ __forceinline__ void split2(float x, float y, uint32_t& hi, uint32_t& lo) {
    __nv_bfloat162 h = __floats2bfloat162_rn(x, y);
    float hx = __bfloat162float(h.x), hy = __bfloat162float(h.y);
    __nv_bfloat162 l = __floats2bfloat162_rn(x - hx, y - hy);
    hi = *(uint32_t*)&h;
    lo = *(uint32_t*)&l;
}

__device__ __forceinline__ float blockReduceSum256(float v, float* sh) {
    #pragma unroll
    for (int o = 16; o > 0; o >>= 1) v += __shfl_xor_sync(0xffffffffu, v, o);
    __syncthreads();
    if ((threadIdx.x & 31) == 0) sh[threadIdx.x >> 5] = v;
    __syncthreads();
    float r = 0.f;
    #pragma unroll
    for (int i = 0; i < 8; i++) r += sh[i];
    return r;
}

__device__ __forceinline__ float blockReduceSum128(float v, float* sh) {
    #pragma unroll
    for (int o = 16; o > 0; o >>= 1) v += __shfl_xor_sync(0xffffffffu, v, o);
    __syncthreads();
    if ((threadIdx.x & 31) == 0) sh[threadIdx.x >> 5] = v;
    __syncthreads();
    return sh[0] + sh[1] + sh[2] + sh[3];
}

// ---------------- 1) LayerNorm of input (rows of 1024) -----------------------
__global__ void ln_input_kernel(const float* __restrict__ x) {
    __shared__ float sh[8];
    size_t base = (size_t)blockIdx.x * DMm;
    float lv[4]; float s = 0.f;
    #pragma unroll
    for (int j = 0; j < 4; j++) { lv[j] = x[base + threadIdx.x + j*256]; s += lv[j]; }
    float mu = blockReduceSum256(s, sh) * (1.f/1024.f);
    float s2 = 0.f;
    #pragma unroll
    for (int j = 0; j < 4; j++) { float d = lv[j] - mu; s2 += d*d; }
    float var = blockReduceSum256(s2, sh) * (1.f/1024.f);
    float rstd = rsqrtf(var + 1e-6f);
    #pragma unroll
    for (int j = 0; j < 4; j++) g_xt[base + threadIdx.x + j*256] = (lv[j]-mu)*rstd;
}

// ---------------- 2a) fp32 FFMA GEMM, 128x64 tile, <=64 regs -----------------
// Dummy dynamic smem pads the block footprint so at most 2 blocks/SM, leaving
// regs + smem for one co-resident tensor-core block. Same accumulation order
// per C element as before (BK=16, k ascending).
__global__ void __launch_bounds__(256, 4)
gemm_ffma_kernel(const float* __restrict__ A, const float* __restrict__ B,
                 float* __restrict__ C, int M, int N, int K) {
    __shared__ float As[16][132];   // [k][m] for 128 rows
    __shared__ float Bs[16][68];    // [k][n] for 64 cols
    extern __shared__ float smem_pad[]; (void)smem_pad;
    int tid  = threadIdx.x;
    int row0 = blockIdx.y * 128;
    int col0 = blockIdx.x * 64;
    int tx = tid & 15, ty = tid >> 4;

    float acc[8][4];
    #pragma unroll
    for (int i = 0; i < 8; i++)
        #pragma unroll
        for (int j = 0; j < 4; j++) acc[i][j] = 0.f;

    for (int k0 = 0; k0 < K; k0 += 16) {
        #pragma unroll
        for (int i = 0; i < 2; i++) {
            int f = tid + i*256;
            int r = f >> 2, c4 = f & 3;
            float4 v = *(const float4*)&A[(size_t)(row0 + r)*K + k0 + c4*4];
            As[c4*4+0][r] = v.x; As[c4*4+1][r] = v.y;
            As[c4*4+2][r] = v.z; As[c4*4+3][r] = v.w;
        }
        {
            int r = tid >> 4, c4 = tid & 15;
            *(float4*)&Bs[r][c4*4] = *(const float4*)&B[(size_t)(k0 + r)*N + col0 + c4*4];
        }
        __syncthreads();
        #pragma unroll
        for (int kk = 0; kk < 16; kk++) {
            float a[8], bb[4];
            *(float4*)&a[0]  = *(float4*)&As[kk][ty*8];
            *(float4*)&a[4]  = *(float4*)&As[kk][ty*8 + 4];
            *(float4*)&bb[0] = *(float4*)&Bs[kk][tx*4];
            #pragma unroll
            for (int i = 0; i < 8; i++)
                #pragma unroll
                for (int j = 0; j < 4; j++) acc[i][j] += a[i]*bb[j];
        }
        __syncthreads();
    }
    #pragma unroll
    for (int i = 0; i < 8; i++)
        *(float4*)&C[(size_t)(row0 + ty*8 + i)*N + col0 + tx*4] =
            make_float4(acc[i][0], acc[i][1], acc[i][2], acc[i][3]);
}

// ---------------- 2b) tf32 1-term GEMM (continuous projections) --------------
__global__ void __launch_bounds__(256, 2)
gemm_tf32_kernel(const float* __restrict__ A, const float* __restrict__ B,
                 float* __restrict__ C, int M, int N, int K) {
    __shared__ float As[128][36];
    __shared__ float Bs[32][132];
    int tid  = threadIdx.x;
    int warp = tid >> 5, lane = tid & 31;
    int g  = lane >> 2, tg = lane & 3;
    int wm = (warp >> 1) * 32;
    int wn = (warp & 1) * 64;
    int row0 = blockIdx.y * 128;
    int col0 = blockIdx.x * 128;

    float c[2][8][4];
    #pragma unroll
    for (int mt = 0; mt < 2; mt++)
        #pragma unroll
        for (int nt = 0; nt < 8; nt++)
            #pragma unroll
            for (int j = 0; j < 4; j++) c[mt][nt][j] = 0.f;

    for (int k0 = 0; k0 < K; k0 += 32) {
        #pragma unroll
        for (int i = 0; i < 4; i++) {
            int f = tid + i*256;
            int r = f >> 3, cc = (f & 7) * 4;
            float4 v = *(const float4*)&A[(size_t)(row0 + r)*K + k0 + cc];
            As[r][cc+0] = to_tf32(v.x); As[r][cc+1] = to_tf32(v.y);
            As[r][cc+2] = to_tf32(v.z); As[r][cc+3] = to_tf32(v.w);
        }
        #pragma unroll
        for (int i = 0; i < 4; i++) {
            int f = tid + i*256;
            int r = f >> 5, cc = (f & 31) * 4;
            float4 v = *(const float4*)&B[(size_t)(k0 + r)*N + col0 + cc];
            Bs[r][cc+0] = to_tf32(v.x); Bs[r][cc+1] = to_tf32(v.y);
            Bs[r][cc+2] = to_tf32(v.z); Bs[r][cc+3] = to_tf32(v.w);
        }
        __syncthreads();
        #pragma unroll
        for (int ks = 0; ks < 4; ks++) {
            int kk = ks * 8;
            uint32_t a[2][4], b[8][2];
            #pragma unroll
            for (int mt = 0; mt < 2; mt++) {
                int m0 = wm + mt*16;
                a[mt][0] = __float_as_uint(As[m0 + g    ][kk + tg    ]);
                a[mt][1] = __float_as_uint(As[m0 + g + 8][kk + tg    ]);
                a[mt][2] = __float_as_uint(As[m0 + g    ][kk + tg + 4]);
                a[mt][3] = __float_as_uint(As[m0 + g + 8][kk + tg + 4]);
            }
            #pragma unroll
            for (int nt = 0; nt < 8; nt++) {
                int n0 = wn + nt*8 + g;
                b[nt][0] = __float_as_uint(Bs[kk + tg    ][n0]);
                b[nt][1] = __float_as_uint(Bs[kk + tg + 4][n0]);
            }
            #pragma unroll
            for (int mt = 0; mt < 2; mt++)
                #pragma unroll
                for (int nt = 0; nt < 8; nt++)
                    mma_tf32(c[mt][nt], a[mt], b[nt]);
        }
        __syncthreads();
    }

    #pragma unroll
    for (int mt = 0; mt < 2; mt++) {
        int row = row0 + wm + mt*16 + g;
        #pragma unroll
        for (int nt = 0; nt < 8; nt++) {
            int col = col0 + wn + nt*8 + tg*2;
            *(float2*)&C[(size_t)row*N + col]     = make_float2(c[mt][nt][0], c[mt][nt][1]);
            *(float2*)&C[(size_t)(row+8)*N + col] = make_float2(c[mt][nt][2], c[mt][nt][3]);
        }
    }
}

// ---------------- 2c) batched NT bf16 3-term GEMM (attention scores) ---------
// C cols written at colOff + col0 with row stride ldC (decoupled from N).
__global__ void __launch_bounds__(256, 2)
gemm_ntbf_kernel(const float* __restrict__ A, const float* __restrict__ B,
                 float* __restrict__ C,
                 size_t strideA, size_t strideB, size_t strideC,
                 int bPerHead, int ldC, int colOff) {
    __shared__ uint32_t Ah[128][20], Al[128][20], Bh[128][20], Bl[128][20];

    int z = blockIdx.z;
    const float* Az = A + (size_t)z * strideA;
    const float* Bz = B + (size_t)(bPerHead ? (z & 7) : z) * strideB;
    float* Cz = C + (size_t)z * strideC;

    int tid  = threadIdx.x;
    int warp = tid >> 5, lane = tid & 31;
    int g  = lane >> 2, tg = lane & 3;
    int wm = (warp >> 1) * 32;
    int wn = (warp & 1) * 64;
    int row0 = blockIdx.y * 128;
    int col0 = blockIdx.x * 128;

    float c[2][8][4];
    #pragma unroll
    for (int mt = 0; mt < 2; mt++)
        #pragma unroll
        for (int nt = 0; nt < 8; nt++)
            #pragma unroll
            for (int j = 0; j < 4; j++) c[mt][nt][j] = 0.f;

    for (int k0 = 0; k0 < 128; k0 += 32) {
        #pragma unroll
        for (int i = 0; i < 4; i++) {
            int f = tid + i*256;
            int r = f >> 3, q4 = f & 7;
            float4 v = *(const float4*)&Az[(size_t)(row0 + r)*128 + k0 + q4*4];
            split2(v.x, v.y, Ah[r][2*q4],   Al[r][2*q4]);
            split2(v.z, v.w, Ah[r][2*q4+1], Al[r][2*q4+1]);
        }
        #pragma unroll
        for (int i = 0; i < 4; i++) {
            int f = tid + i*256;
            int r = f >> 3, q4 = f & 7;
            float4 v = *(const float4*)&Bz[(size_t)(col0 + r)*128 + k0 + q4*4];
            split2(v.x, v.y, Bh[r][2*q4],   Bl[r][2*q4]);
            split2(v.z, v.w, Bh[r][2*q4+1], Bl[r][2*q4+1]);
        }
        __syncthreads();
        #pragma unroll
        for (int c16 = 0; c16 < 2; c16++) {
            int coff = c16 * 8;
            uint32_t ah[2][4], al[2][4];
            #pragma unroll
            for (int mt = 0; mt < 2; mt++) {
                int m0 = wm + mt*16;
                ah[mt][0] = Ah[m0 + g    ][coff + tg    ];
                ah[mt][1] = Ah[m0 + g + 8][coff + tg    ];
                ah[mt][2] = Ah[m0 + g    ][coff + tg + 4];
                ah[mt][3] = Ah[m0 + g + 8][coff + tg + 4];
                al[mt][0] = Al[m0 + g    ][coff + tg    ];
                al[mt][1] = Al[m0 + g + 8][coff + tg    ];
                al[mt][2] = Al[m0 + g    ][coff + tg + 4];
                al[mt][3] = Al[m0 + g + 8][coff + tg + 4];
            }
            #pragma unroll
            for (int nt = 0; nt < 8; nt++) {
                int n0 = wn + nt*8 + g;
                uint32_t bh[2], bl[2];
                bh[0] = Bh[n0][coff + tg    ];
                bh[1] = Bh[n0][coff + tg + 4];
                bl[0] = Bl[n0][coff + tg    ];
                bl[1] = Bl[n0][coff + tg + 4];
                #pragma unroll
                for (int mt = 0; mt < 2; mt++) {
                    mma_bf16(c[mt][nt], ah[mt], bh);
                    mma_bf16(c[mt][nt], ah[mt], bl);
                    mma_bf16(c[mt][nt], al[mt], bh);
                }
            }
        }
        __syncthreads();
    }

    #pragma unroll
    for (int mt = 0; mt < 2; mt++) {
        int row = row0 + wm + mt*16 + g;
        #pragma unroll
        for (int nt = 0; nt < 8; nt++) {
            int col = colOff + col0 + wn + nt*8 + tg*2;
            *(float2*)&Cz[(size_t)row*ldC + col]     = make_float2(c[mt][nt][0], c[mt][nt][1]);
            *(float2*)&Cz[(size_t)(row+8)*ldC + col] = make_float2(c[mt][nt][2], c[mt][nt][3]);
        }
    }
}

// ---------------- 2d) batched NN bf16 3-term value GEMM, gated epilogue ------
__global__ void __launch_bounds__(256, 2)
gemm_valbf_kernel() {
    __shared__ uint32_t Ah[128][20], Al[128][20];
    __shared__ uint32_t BhT[16][136], BlT[16][136];

    int z = blockIdx.z;
    int b = z >> 3, h = z & 7;
    const float* Az = g_S1 + (size_t)z * Ll * WTOT;
    const float* Bz = g_vals + (size_t)z * WTOT * DVv;

    int tid  = threadIdx.x;
    int warp = tid >> 5, lane = tid & 31;
    int g  = lane >> 2, tg = lane & 3;
    int wm = (warp >> 1) * 32;
    int wn = (warp & 1) * 64;
    int row0 = blockIdx.y * 128;

    float c[2][8][4];
    #pragma unroll
    for (int mt = 0; mt < 2; mt++)
        #pragma unroll
        for (int nt = 0; nt < 8; nt++)
            #pragma unroll
            for (int j = 0; j < 4; j++) c[mt][nt][j] = 0.f;

    for (int k0 = 0; k0 < WTOT; k0 += 32) {
        #pragma unroll
        for (int i = 0; i < 4; i++) {
            int f = tid + i*256;
            int r = f >> 3, q4 = f & 7;
            float4 v = *(const float4*)&Az[(size_t)(row0 + r)*WTOT + k0 + q4*4];
            split2(v.x, v.y, Ah[r][2*q4],   Al[r][2*q4]);
            split2(v.z, v.w, Ah[r][2*q4+1], Al[r][2*q4+1]);
        }
        #pragma unroll
        for (int i = 0; i < 2; i++) {
            int f = tid + i*256;
            int kp = f >> 5, n4 = f & 31;
            float4 v0 = *(const float4*)&Bz[(size_t)(k0 + 2*kp    )*128 + n4*4];
            float4 v1 = *(const float4*)&Bz[(size_t)(k0 + 2*kp + 1)*128 + n4*4];
            split2(v0.x, v1.x, BhT[kp][4*n4+0], BlT[kp][4*n4+0]);
            split2(v0.y, v1.y, BhT[kp][4*n4+1], BlT[kp][4*n4+1]);
            split2(v0.z, v1.z, BhT[kp][4*n4+2], BlT[kp][4*n4+2]);
            split2(v0.w, v1.w, BhT[kp][4*n4+3], BlT[kp][4*n4+3]);
        }
        __syncthreads();
        #pragma unroll
        for (int c16 = 0; c16 < 2; c16++) {
            int coff = c16 * 8;
            uint32_t ah[2][4], al[2][4];
            #pragma unroll
            for (int mt = 0; mt < 2; mt++) {
                int m0 = wm + mt*16;
                ah[mt][0] = Ah[m0 + g    ][coff + tg    ];
                ah[mt][1] = Ah[m0 + g + 8][coff + tg    ];
                ah[mt][2] = Ah[m0 + g    ][coff + tg + 4];
                ah[mt][3] = Ah[m0 + g + 8][coff + tg + 4];
                al[mt][0] = Al[m0 + g    ][coff + tg    ];
                al[mt][1] = Al[m0 + g + 8][coff + tg    ];
                al[mt][2] = Al[m0 + g    ][coff + tg + 4];
                al[mt][3] = Al[m0 + g + 8][coff + tg + 4];
            }
            #pragma unroll
            for (int nt = 0; nt < 8; nt++) {
                int n0 = wn + nt*8 + g;
                uint32_t bh[2], bl[2];
                bh[0] = BhT[coff + tg    ][n0];
                bh[1] = BhT[coff + tg + 4][n0];
                bl[0] = BlT[coff + tg    ][n0];
                bl[1] = BlT[coff + tg + 4][n0];
                #pragma unroll
                for (int mt = 0; mt < 2; mt++) {
                    mma_bf16(c[mt][nt], ah[mt], bh);
                    mma_bf16(c[mt][nt], ah[mt], bl);
                    mma_bf16(c[mt][nt], al[mt], bh);
                }
            }
        }
        __syncthreads();
    }

    #pragma unroll
    for (int mt = 0; mt < 2; mt++) {
        int row = row0 + wm + mt*16 + g;
        #pragma unroll
        for (int nt = 0; nt < 8; nt++) {
            int col = wn + nt*8 + tg*2;
            size_t o0 = ((size_t)(b*Ll + row))*1024 + h*128 + col;
            size_t o1 = ((size_t)(b*Ll + row + 8))*1024 + h*128 + col;
            float2 g0 = *(const float2*)&g_g[o0];
            float2 g1 = *(const float2*)&g_g[o1];
            *(float2*)&g_wvg[o0] = make_float2(c[mt][nt][0]*g0.x, c[mt][nt][1]*g0.y);
            *(float2*)&g_wvg[o1] = make_float2(c[mt][nt][2]*g1.x, c[mt][nt][3]*g1.y);
        }
    }
}

// ---------------- 3a) k LN only (side chain) ---------------------------------
__global__ void kln_kernel() {
    __shared__ float sh[4];
    int bl = blockIdx.x, h = blockIdx.y, t = threadIdx.x;
    int b = bl >> 9, l = bl & 511;
    size_t bh = (size_t)(b*Hh + h);

    float x  = g_kvg[(size_t)bl*3072 + h*128 + t];
    float mu = blockReduceSum128(x, sh) * (1.f/128.f);
    float d  = x - mu;
    float var = blockReduceSum128(d*d, sh) * (1.f/128.f);
    g_kn[(bh*Ll + l)*128 + t] = d * rsqrtf(var + 1e-6f);
}

// ---------------- 3b) q LN + qu/qv, v copy, gate (main chain) ----------------
__global__ void qgate_kernel(const float* __restrict__ xu, const float* __restrict__ xv) {
    __shared__ float sh[4];
    int bl = blockIdx.x, h = blockIdx.y, t = threadIdx.x;
    int b = bl >> 9, l = bl & 511;
    size_t bh = (size_t)(b*Hh + h);

    float x  = g_qraw[(size_t)bl*1024 + h*128 + t];
    float mu = blockReduceSum128(x, sh) * (1.f/128.f);
    float d  = x - mu;
    float var = blockReduceSum128(d*d, sh) * (1.f/128.f);
    float qn = d * rsqrtf(var + 1e-6f);
    g_qu[(bh*Ll + l)*128 + t] = qn + xu[h*128 + t];
    g_qv[(bh*Ll + l)*128 + t] = qn + xv[h*128 + t];

    g_vals[(bh*WTOT + Mm + l)*128 + t] = g_kvg[(size_t)bl*3072 + 1024 + h*128 + t];

    float gx = g_kvg[(size_t)bl*3072 + 2048 + h*128 + t];
    g_g[(size_t)bl*1024 + h*128 + t] = gx / (1.f + __expf(-gx));
}

// ---------------- 4) VQ argmin over 512 codes (fp32 FFMA, proven) ------------
__global__ void vq_kernel(const float* __restrict__ codebook) {
    __shared__ float ks[16][128];
    __shared__ float redv[16][256];
    __shared__ int   redi[16][256];
    int bh = blockIdx.x, lt = blockIdx.y;
    int h  = bh & 7;
    int tid = threadIdx.x;
    #pragma unroll
    for (int j = 0; j < 2; j++) {
        int f = tid + j*256;
        int r = f >> 5, c4 = f & 31;
        *(float4*)&ks[r][c4*4] =
            *(const float4*)&g_kn[((size_t)bh*Ll + lt*16 + r)*128 + c4*4];
    }
    __syncthreads();

    float best[16]; int bidx[16];
    #pragma unroll
    for (int r = 0; r < 16; r++) { best[r] = 3.4e38f; bidx[r] = 0; }

    for (int s = tid; s < Ss; s += 256) {
        const float4* c = (const float4*)(codebook + ((size_t)h*Ss + s)*128);
        float cc = 0.f; float acc[16];
        #pragma unroll
        for (int r = 0; r < 16; r++) acc[r] = 0.f;
        #pragma unroll 4
        for (int d4 = 0; d4 < 32; d4++) {
            float4 cv = c[d4];
            cc += cv.x*cv.x + cv.y*cv.y + cv.z*cv.z + cv.w*cv.w;
            #pragma unroll
            for (int r = 0; r < 16; r++) {
                float4 kv = *(float4*)&ks[r][d4*4];
                acc[r] += cv.x*kv.x + cv.y*kv.y + cv.z*kv.z + cv.w*kv.w;
            }
        }
        #pragma unroll
        for (int r = 0; r < 16; r++) {
            float d2 = cc - 2.f*acc[r];
            if (d2 < best[r]) { best[r] = d2; bidx[r] = s; }
        }
    }
    #pragma unroll
    for (int r = 0; r < 16; r++) { redv[r][tid] = best[r]; redi[r][tid] = bidx[r]; }
    __syncthreads();

    int warp = tid >> 5, lane = tid & 31;
    for (int r = warp*2; r < warp*2 + 2; r++) {
        float bv = 3.4e38f; int bi = 0x7fffffff;
        for (int t = lane; t < 256; t += 32) {
            float v = redv[r][t]; int i = redi[r][t];
            if (v < bv || (v == bv && i < bi)) { bv = v; bi = i; }
        }
        #pragma unroll
        for (int o = 16; o > 0; o >>= 1) {
            float ov = __shfl_xor_sync(0xffffffffu, bv, o);
            int   oi = __shfl_xor_sync(0xffffffffu, bi, o);
            if (ov < bv || (ov == bv && oi < bi)) { bv = ov; bi = oi; }
        }
        if (lane == 0) g_z[(size_t)bh*Ll + lt*16 + r] = bi;
    }
}

// ---------------- 5) assemble vals from inputs only --------------------------
__global__ void assembleV_kernel(const float* __restrict__ xlv,
                                 const float* __restrict__ aggU) {
    for (int e = blockIdx.x*blockDim.x + threadIdx.x; e < Bb*Hh*Mm*DKk;
         e += gridDim.x*blockDim.x) {
        int bh  = e >> 16;
        int rem = e & 65535;
        int m = rem >> 7, d = rem & 127;
        g_vals[((size_t)bh*WTOT + m)*128 + d] = xlv[e];
        g_vals[((size_t)bh*WTOT + WREC + m)*128 + d] = aggU[e];
    }
}

// ---------------- 5b) gather c_z score columns from codebook score block -----
// S1[l][512+m] = S1[l][1024 + z[bh][m]]  (bitwise identical to GEMM vs cb[z[m]])
__global__ void gather_cz_kernel() {
    int l = blockIdx.x, z = blockIdx.y, m = threadIdx.x;
    int s = g_z[(size_t)z*Ll + m];
    float* row = g_S1 + ((size_t)z*Ll + l)*WTOT;
    row[512 + m] = row[1024 + s];
}

// ---------------- 6) softmax: combine AC + shifted BD + cache bias -----------
__global__ void softmax_kernel(const float* __restrict__ aggL) {
    __shared__ float red[4];
    int l = blockIdx.x, z = blockIdx.y, tid = threadIdx.x;
    float* S1row = g_S1 + ((size_t)z*Ll + l)*WTOT;
    const float* S2row = g_S2 + ((size_t)z*Ll + l)*WREC;
    int limit = l + Mm;

    float sv[12];
    float m = -3.4e38f;
    #pragma unroll
    for (int i = 0; i < 12; i++) {
        int w = tid + i*128;
        float s;
        if (w < WREC) {
            s = (w <= limit) ? (S1row[w] + S2row[w + 511 - l]) * INVTAU : -3.4e38f;
        } else {
            float al = aggL[(size_t)z*Ss + (w - WREC)];
            float bias = (al > 0.f) ? logf(fmaxf(al, 1e-30f)) : -1e30f;
            s = S1row[w] * INVTAU + bias;
        }
        sv[i] = s;
        m = fmaxf(m, s);
    }
    #pragma unroll
    for (int o = 16; o > 0; o >>= 1) m = fmaxf(m, __shfl_xor_sync(0xffffffffu, m, o));
    if ((tid & 31) == 0) red[tid >> 5] = m;
    __syncthreads();
    m = fmaxf(fmaxf(red[0], red[1]), fmaxf(red[2], red[3]));
    __syncthreads();

    float ssum = 0.f;
    #pragma unroll
    for (int i = 0; i < 12; i++) {
        float p = (sv[i] > -1e37f) ? __expf(sv[i] - m) : 0.f;
        sv[i] = p;
        ssum += p;
    }
    #pragma unroll
    for (int o = 16; o > 0; o >>= 1) ssum += __shfl_xor_sync(0xffffffffu, ssum, o);
    if ((tid & 31) == 0) red[tid >> 5] = ssum;
    __syncthreads();
    float invd = 1.f / (red[0] + red[1] + red[2] + red[3]);

    #pragma unroll
    for (int i = 0; i < 12; i++) S1row[tid + i*128] = sv[i] * invd;
}

// ---------------- launch ------------------------------------------------------
extern "C" void kernel_launch(void* const* d_in, const int* in_sizes, int n_in,
                              void* d_out, int out_size) {
    const float* input = (const float*)d_in[0];
    const float* xlk   = (const float*)d_in[2];
    const float* xlv   = (const float*)d_in[3];
    const float* aggU  = (const float*)d_in[4];
    const float* aggL  = (const float*)d_in[5];
    const float* Wq    = (const float*)d_in[6];
    const float* Wkvg  = (const float*)d_in[7];
    const float* Wres  = (const float*)d_in[8];
    const float* xu    = (const float*)d_in[9];
    const float* xv    = (const float*)d_in[10];
    const float* xlr   = (const float*)d_in[11];
    const float* cb    = (const float*)d_in[12];
    float* out = (float*)d_out;

    float *xt, *qraw, *kvg, *wvg, *qu, *qv, *S1, *S2;
    cudaGetSymbolAddress((void**)&xt,   g_xt);
    cudaGetSymbolAddress((void**)&qraw, g_qraw);
    cudaGetSymbolAddress((void**)&kvg,  g_kvg);
    cudaGetSymbolAddress((void**)&wvg,  g_wvg);
    cudaGetSymbolAddress((void**)&qu,   g_qu);
    cudaGetSymbolAddress((void**)&qv,   g_qv);
    cudaGetSymbolAddress((void**)&S1,   g_S1);
    cudaGetSymbolAddress((void**)&S2,   g_S2);

    // smem pad so at most 2 ffma blocks/SM, leaving room for one tensor block
    const int FFMA_PAD = 80 * 1024;
    cudaFuncSetAttribute(gemm_ffma_kernel,
                         cudaFuncAttributeMaxDynamicSharedMemorySize, FFMA_PAD);

    // side stream + events, created once (first call runs eagerly, pre-capture)
    static cudaStream_t sA = nullptr;
    static cudaEvent_t evFork, evSide;
    if (sA == nullptr) {
        cudaStreamCreateWithFlags(&sA, cudaStreamNonBlocking);
        cudaEventCreateWithFlags(&evFork, cudaEventDisableTiming);
        cudaEventCreateWithFlags(&evSide, cudaEventDisableTiming);
    }

    // ---- stage 0 (main): input-only vals assembly + input LN ----
    assembleV_kernel<<<2048, 256>>>(xlv, aggU);
    ln_input_kernel<<<Bb*Ll, 256>>>(input);
    cudaEventRecord(evFork, 0);
    cudaStreamWaitEvent(sA, evFork, 0);

    // ---- side chain: fp32 k-proj -> k LN -> VQ argmin ----
    gemm_ffma_kernel<<<dim3(16, 32), 256, FFMA_PAD, sA>>>(xt, Wkvg, kvg,
                                                          4096, 3072, 1024);
    kln_kernel<<<dim3(Bb*Ll, Hh), 128, 0, sA>>>();
    vq_kernel<<<dim3(Bb*Hh, Ll/16), 256, 0, sA>>>(cb);
    cudaEventRecord(evSide, sA);

    // ---- main chain: tensor projections, gates, all z-free score GEMMs ----
    gemm_tf32_kernel<<<dim3(1024/128, 4096/128), 256>>>(xt, Wq, qraw, 4096, 1024, 1024);
    gemm_tf32_kernel<<<dim3(2048/128, 4096/128), 256>>>(xt, Wkvg + 1024, kvg + 1024,
                                                        4096, 3072, 1024);
    qgate_kernel<<<dim3(Bb*Ll, Hh), 128>>>(xu, xv);
    // S2 = qv @ xlr^T   (B per head)
    gemm_ntbf_kernel<<<dim3(WREC/128, Ll/128, 64), 256>>>(
        qv, xlr, S2,
        (size_t)Ll*128, (size_t)WREC*128, (size_t)Ll*WREC, 1, WREC, 0);
    // S1 xlk block: cols [0,512)
    gemm_ntbf_kernel<<<dim3(512/128, Ll/128, 64), 256>>>(
        qu, xlk, S1,
        (size_t)Ll*128, (size_t)Mm*128, (size_t)Ll*WTOT, 0, WTOT, 0);
    // S1 codebook block: cols [1024,1536)
    gemm_ntbf_kernel<<<dim3(512/128, Ll/128, 64), 256>>>(
        qu, cb, S1,
        (size_t)Ll*128, (size_t)Ss*128, (size_t)Ll*WTOT, 1, WTOT, 1024);

    // ---- join: c_z columns are a gather of the codebook block ----
    cudaStreamWaitEvent(0, evSide, 0);
    gather_cz_kernel<<<dim3(Ll, 64), 512>>>();

    softmax_kernel<<<dim3(Ll, 64), 128>>>(aggL);
    gemm_valbf_kernel<<<dim3(1, Ll/128, 64), 256>>>();
    gemm_tf32_kernel<<<dim3(1024/128, 4096/128), 256>>>(wvg, Wres, out, 4096, 1024, 1024);
}

// round 11
// speedup vs baseline: 1.1128x; 1.1128x over previous
#include <cuda_runtime.h>
#include <cuda_bf16.h>
#include <math.h>
#include <stdint.h>

// Shapes (fixed for this problem)
#define Bb   8
#define Ll   512
#define Mm   512
#define Hh   8
#define DKk  128
#define DVv  128
#define Ss   512
#define DMm  1024
#define WREC 1024
#define WTOT 1536    // recent 1024 + cache 512

#define INVTAU 0.08838834764831845f   // 1/sqrt(128)
#define TAU_GAP 0.01f

// ---------------- scratch (device globals; no allocation allowed) ------------
__device__ float g_xt  [Bb*Ll*DMm];
__device__ float g_qraw[Bb*Ll*Hh*DKk];
__device__ float g_kvg [Bb*Ll*3072];
__device__ float g_kn  [Bb*Hh*Ll*DKk];
__device__ float g_g   [Bb*Ll*Hh*DVv];
__device__ float g_qu  [64*Ll*DKk];          // q + x_u  (b,h,l,d)
__device__ float g_qv  [64*Ll*DKk];          // q + x_v
__device__ float g_vals[64*WTOT*DVv];        // [xl_v; v; agg_upper]
__device__ float g_S1  [(size_t)64*Ll*WTOT]; // scores -> probs
__device__ float g_S2  [(size_t)64*Ll*WREC]; // VQ scores scratch, then BD term
__device__ float g_wvg [Bb*Ll*Hh*DVv];
__device__ float g_cc  [Hh*Ss];              // ||codebook||^2
__device__ int   g_z   [Bb*Hh*Ll];

// ---------------- helpers ----------------------------------------------------
__device__ __forceinline__ uint32_t tf32_of(float x) {
    uint32_t u;
    asm("cvt.rna.tf32.f32 %0, %1;" : "=r"(u) : "f"(x));
    return u;
}

__device__ __forceinline__ uint32_t smem_u32(const void* p) {
    return (uint32_t)__cvta_generic_to_shared(p);
}
#define CP_ASYNC16(dst, src) \
    asm volatile("cp.async.cg.shared.global [%0], [%1], 16;" :: "r"(dst), "l"(src))
#define CP_COMMIT() asm volatile("cp.async.commit_group;")
#define CP_WAIT1()  asm volatile("cp.async.wait_group 1;")
#define CP_WAIT0()  asm volatile("cp.async.wait_group 0;")

__device__ __forceinline__ void mma_tf32(float* c, const uint32_t* a, const uint32_t* b) {
    asm volatile(
        "mma.sync.aligned.m16n8k8.row.col.f32.tf32.tf32.f32 "
        "{%0,%1,%2,%3}, {%4,%5,%6,%7}, {%8,%9}, {%0,%1,%2,%3};"
        : "+f"(c[0]), "+f"(c[1]), "+f"(c[2]), "+f"(c[3])
        : "r"(a[0]), "r"(a[1]), "r"(a[2]), "r"(a[3]), "r"(b[0]), "r"(b[1]));
}

__device__ __forceinline__ void mma_bf16(float* c, const uint32_t* a, const uint32_t* b) {
    asm volatile(
        "mma.sync.aligned.m16n8k16.row.col.f32.bf16.bf16.f32 "
        "{%0,%1,%2,%3}, {%4,%5,%6,%7}, {%8,%9}, {%0,%1,%2,%3};"
        : "+f"(c[0]), "+f"(c[1]), "+f"(c[2]), "+f"(c[3])
        : "r"(a[0]), "r"(a[1]), "r"(a[2]), "r"(a[3]), "r"(b[0]), "r"(b[1]));
}

// split two floats into packed bf16x2 hi and lo words (k-pair: x->low, y->high)
__device__ __forceinline__ void split2(float x, float y, uint32_t& hi, uint32_t& lo) {
    __nv_bfloat162 h = __floats2bfloat162_rn(x, y);
    float hx = __bfloat162float(h.x), hy = __bfloat162float(h.y);
    __nv_bfloat162 l = __floats2bfloat162_rn(x - hx, y - hy);
    hi = *(uint32_t*)&h;
    lo = *(uint32_t*)&l;
}

__device__ __forceinline__ float blockReduceSum256(float v, float* sh) {
    #pragma unroll
    for (int o = 16; o > 0; o >>= 1) v += __shfl_xor_sync(0xffffffffu, v, o);
    __syncthreads();
    if ((threadIdx.x & 31) == 0) sh[threadIdx.x >> 5] = v;
    __syncthreads();
    float r = 0.f;
    #pragma unroll
    for (int i = 0; i < 8; i++) r += sh[i];
    return r;
}

__device__ __forceinline__ float blockReduceSum128(float v, float* sh) {
    #pragma unroll
    for (int o = 16; o > 0; o >>= 1) v += __shfl_xor_sync(0xffffffffu, v, o);
    __syncthreads();
    if ((threadIdx.x & 31) == 0) sh[threadIdx.x >> 5] = v;
    __syncthreads();
    return sh[0] + sh[1] + sh[2] + sh[3];
}

// ---------------- 1) LayerNorm of input (rows of 1024) -----------------------
__global__ void ln_input_kernel(const float* __restrict__ x) {
    __shared__ float sh[8];
    size_t base = (size_t)blockIdx.x * DMm;
    float lv[4]; float s = 0.f;
    #pragma unroll
    for (int j = 0; j < 4; j++) { lv[j] = x[base + threadIdx.x + j*256]; s += lv[j]; }
    float mu = blockReduceSum256(s, sh) * (1.f/1024.f);
    float s2 = 0.f;
    #pragma unroll
    for (int j = 0; j < 4; j++) { float d = lv[j] - mu; s2 += d*d; }
    float var = blockReduceSum256(s2, sh) * (1.f/1024.f);
    float rstd = rsqrtf(var + 1e-6f);
    #pragma unroll
    for (int j = 0; j < 4; j++) g_xt[base + threadIdx.x + j*256] = (lv[j]-mu)*rstd;
}

// ---------------- 2a) fp32 FFMA GEMM (full precision, k-columns) -------------
__global__ void __launch_bounds__(256, 2)
gemm_ffma_kernel(const float* __restrict__ A, const float* __restrict__ B,
                 float* __restrict__ C, int M, int N, int K) {
    __shared__ float As[16][132];
    __shared__ float Bs[16][132];
    int tid  = threadIdx.x;
    int row0 = blockIdx.y * 128;
    int col0 = blockIdx.x * 128;
    int tx = tid & 15, ty = tid >> 4;

    float acc[8][8];
    #pragma unroll
    for (int i = 0; i < 8; i++)
        #pragma unroll
        for (int j = 0; j < 8; j++) acc[i][j] = 0.f;

    for (int k0 = 0; k0 < K; k0 += 16) {
        #pragma unroll
        for (int i = 0; i < 2; i++) {
            int f = tid + i*256;
            int r = f >> 2, c4 = f & 3;
            float4 v = *(const float4*)&A[(size_t)(row0 + r)*K + k0 + c4*4];
            As[c4*4+0][r] = v.x; As[c4*4+1][r] = v.y;
            As[c4*4+2][r] = v.z; As[c4*4+3][r] = v.w;
        }
        #pragma unroll
        for (int i = 0; i < 2; i++) {
            int f = tid + i*256;
            int r = f >> 5, c4 = f & 31;
            *(float4*)&Bs[r][c4*4] = *(const float4*)&B[(size_t)(k0 + r)*N + col0 + c4*4];
        }
        __syncthreads();
        #pragma unroll
        for (int kk = 0; kk < 16; kk++) {
            float a[8], bb[8];
            *(float4*)&a[0]  = *(float4*)&As[kk][ty*8];
            *(float4*)&a[4]  = *(float4*)&As[kk][ty*8 + 4];
            *(float4*)&bb[0] = *(float4*)&Bs[kk][tx*4];
            *(float4*)&bb[4] = *(float4*)&Bs[kk][64 + tx*4];
            #pragma unroll
            for (int i = 0; i < 8; i++)
                #pragma unroll
                for (int j = 0; j < 8; j++) acc[i][j] += a[i]*bb[j];
        }
        __syncthreads();
    }
    #pragma unroll
    for (int i = 0; i < 8; i++) {
        size_t crow = (size_t)(row0 + ty*8 + i)*N;
        *(float4*)&C[crow + col0 + tx*4]      = make_float4(acc[i][0], acc[i][1], acc[i][2], acc[i][3]);
        *(float4*)&C[crow + col0 + 64 + tx*4] = make_float4(acc[i][4], acc[i][5], acc[i][6], acc[i][7]);
    }
}

// ---------------- 2b) tf32 1-term GEMM, cp.async double-buffered -------------
// dyn smem: As[2][128][36] + Bs[2][32][132] raw fp32; cvt.rna at fragment load.
__global__ void __launch_bounds__(256, 2)
gemm_tf32_kernel(const float* __restrict__ A, const float* __restrict__ B,
                 float* __restrict__ C, int M, int N, int K) {
    extern __shared__ float sm[];
    const int ASZ = 128*36, BSZ = 32*132;
    int tid  = threadIdx.x;
    int warp = tid >> 5, lane = tid & 31;
    int g  = lane >> 2, tg = lane & 3;
    int wm = (warp >> 1) * 32;
    int wn = (warp & 1) * 64;
    int row0 = blockIdx.y * 128;
    int col0 = blockIdx.x * 128;

    float c[2][8][4];
    #pragma unroll
    for (int mt = 0; mt < 2; mt++)
        #pragma unroll
        for (int nt = 0; nt < 8; nt++)
            #pragma unroll
            for (int j = 0; j < 4; j++) c[mt][nt][j] = 0.f;

    // stage k0 into buffer buf (async)
    #define STAGE(k0_, buf_) do {                                              \
        float* As_ = sm + (buf_)*ASZ;                                          \
        float* Bs_ = sm + 2*ASZ + (buf_)*BSZ;                                  \
        _Pragma("unroll")                                                      \
        for (int i_ = 0; i_ < 4; i_++) {                                       \
            int f_ = tid + i_*256;                                             \
            int r_ = f_ >> 3, c4_ = (f_ & 7) * 4;                              \
            CP_ASYNC16(smem_u32(&As_[r_*36 + c4_]),                            \
                       &A[(size_t)(row0 + r_)*K + (k0_) + c4_]);               \
        }                                                                      \
        _Pragma("unroll")                                                      \
        for (int i_ = 0; i_ < 4; i_++) {                                       \
            int f_ = tid + i_*256;                                             \
            int r_ = f_ >> 5, c4_ = (f_ & 31) * 4;                             \
            CP_ASYNC16(smem_u32(&Bs_[r_*132 + c4_]),                           \
                       &B[(size_t)((k0_) + r_)*N + col0 + c4_]);               \
        }                                                                      \
    } while (0)

    STAGE(0, 0); CP_COMMIT();

    for (int k0 = 0; k0 < K; k0 += 32) {
        int buf = (k0 >> 5) & 1;
        if (k0 + 32 < K) { STAGE(k0 + 32, buf ^ 1); CP_COMMIT(); CP_WAIT1(); }
        else             { CP_WAIT0(); }
        __syncthreads();
        float* As = sm + buf*ASZ;
        float* Bs = sm + 2*ASZ + buf*BSZ;
        #pragma unroll
        for (int ks = 0; ks < 4; ks++) {
            int kk = ks * 8;
            uint32_t a[2][4], b[8][2];
            #pragma unroll
            for (int mt = 0; mt < 2; mt++) {
                int m0 = wm + mt*16;
                a[mt][0] = tf32_of(As[(m0 + g    )*36 + kk + tg    ]);
                a[mt][1] = tf32_of(As[(m0 + g + 8)*36 + kk + tg    ]);
                a[mt][2] = tf32_of(As[(m0 + g    )*36 + kk + tg + 4]);
                a[mt][3] = tf32_of(As[(m0 + g + 8)*36 + kk + tg + 4]);
            }
            #pragma unroll
            for (int nt = 0; nt < 8; nt++) {
                int n0 = wn + nt*8 + g;
                b[nt][0] = tf32_of(Bs[(kk + tg    )*132 + n0]);
                b[nt][1] = tf32_of(Bs[(kk + tg + 4)*132 + n0]);
            }
            #pragma unroll
            for (int mt = 0; mt < 2; mt++)
                #pragma unroll
                for (int nt = 0; nt < 8; nt++)
                    mma_tf32(c[mt][nt], a[mt], b[nt]);
        }
        __syncthreads();
    }
    #undef STAGE

    #pragma unroll
    for (int mt = 0; mt < 2; mt++) {
        int row = row0 + wm + mt*16 + g;
        #pragma unroll
        for (int nt = 0; nt < 8; nt++) {
            int col = col0 + wn + nt*8 + tg*2;
            *(float2*)&C[(size_t)row*N + col]     = make_float2(c[mt][nt][0], c[mt][nt][1]);
            *(float2*)&C[(size_t)(row+8)*N + col] = make_float2(c[mt][nt][2], c[mt][nt][3]);
        }
    }
}

// ---------------- 2c) batched NT bf16 3-term GEMM ----------------------------
// C cols written at colOff + col0 with row stride ldC.
__global__ void __launch_bounds__(256, 2)
gemm_ntbf_kernel(const float* __restrict__ A, const float* __restrict__ B,
                 float* __restrict__ C,
                 size_t strideA, size_t strideB, size_t strideC,
                 int bPerHead, int ldC, int colOff) {
    __shared__ uint32_t Ah[128][20], Al[128][20], Bh[128][20], Bl[128][20];

    int z = blockIdx.z;
    const float* Az = A + (size_t)z * strideA;
    const float* Bz = B + (size_t)(bPerHead ? (z & 7) : z) * strideB;
    float* Cz = C + (size_t)z * strideC;

    int tid  = threadIdx.x;
    int warp = tid >> 5, lane = tid & 31;
    int g  = lane >> 2, tg = lane & 3;
    int wm = (warp >> 1) * 32;
    int wn = (warp & 1) * 64;
    int row0 = blockIdx.y * 128;
    int col0 = blockIdx.x * 128;

    float c[2][8][4];
    #pragma unroll
    for (int mt = 0; mt < 2; mt++)
        #pragma unroll
        for (int nt = 0; nt < 8; nt++)
            #pragma unroll
            for (int j = 0; j < 4; j++) c[mt][nt][j] = 0.f;

    for (int k0 = 0; k0 < 128; k0 += 32) {
        #pragma unroll
        for (int i = 0; i < 4; i++) {
            int f = tid + i*256;
            int r = f >> 3, q4 = f & 7;
            float4 v = *(const float4*)&Az[(size_t)(row0 + r)*128 + k0 + q4*4];
            split2(v.x, v.y, Ah[r][2*q4],   Al[r][2*q4]);
            split2(v.z, v.w, Ah[r][2*q4+1], Al[r][2*q4+1]);
        }
        #pragma unroll
        for (int i = 0; i < 4; i++) {
            int f = tid + i*256;
            int r = f >> 3, q4 = f & 7;
            float4 v = *(const float4*)&Bz[(size_t)(col0 + r)*128 + k0 + q4*4];
            split2(v.x, v.y, Bh[r][2*q4],   Bl[r][2*q4]);
            split2(v.z, v.w, Bh[r][2*q4+1], Bl[r][2*q4+1]);
        }
        __syncthreads();
        #pragma unroll
        for (int c16 = 0; c16 < 2; c16++) {
            int coff = c16 * 8;
            uint32_t ah[2][4], al[2][4];
            #pragma unroll
            for (int mt = 0; mt < 2; mt++) {
                int m0 = wm + mt*16;
                ah[mt][0] = Ah[m0 + g    ][coff + tg    ];
                ah[mt][1] = Ah[m0 + g + 8][coff + tg    ];
                ah[mt][2] = Ah[m0 + g    ][coff + tg + 4];
                ah[mt][3] = Ah[m0 + g + 8][coff + tg + 4];
                al[mt][0] = Al[m0 + g    ][coff + tg    ];
                al[mt][1] = Al[m0 + g + 8][coff + tg    ];
                al[mt][2] = Al[m0 + g    ][coff + tg + 4];
                al[mt][3] = Al[m0 + g + 8][coff + tg + 4];
            }
            #pragma unroll
            for (int nt = 0; nt < 8; nt++) {
                int n0 = wn + nt*8 + g;
                uint32_t bh[2], bl[2];
                bh[0] = Bh[n0][coff + tg    ];
                bh[1] = Bh[n0][coff + tg + 4];
                bl[0] = Bl[n0][coff + tg    ];
                bl[1] = Bl[n0][coff + tg + 4];
                #pragma unroll
                for (int mt = 0; mt < 2; mt++) {
                    mma_bf16(c[mt][nt], ah[mt], bh);
                    mma_bf16(c[mt][nt], ah[mt], bl);
                    mma_bf16(c[mt][nt], al[mt], bh);
                }
            }
        }
        __syncthreads();
    }

    #pragma unroll
    for (int mt = 0; mt < 2; mt++) {
        int row = row0 + wm + mt*16 + g;
        #pragma unroll
        for (int nt = 0; nt < 8; nt++) {
            int col = colOff + col0 + wn + nt*8 + tg*2;
            *(float2*)&Cz[(size_t)row*ldC + col]     = make_float2(c[mt][nt][0], c[mt][nt][1]);
            *(float2*)&Cz[(size_t)(row+8)*ldC + col] = make_float2(c[mt][nt][2], c[mt][nt][3]);
        }
    }
}

// ---------------- 2d) batched NN bf16 3-term value GEMM, gated epilogue ------
__global__ void __launch_bounds__(256, 2)
gemm_valbf_kernel() {
    __shared__ uint32_t Ah[128][20], Al[128][20];
    __shared__ uint32_t BhT[16][136], BlT[16][136];

    int z = blockIdx.z;
    int b = z >> 3, h = z & 7;
    const float* Az = g_S1 + (size_t)z * Ll * WTOT;
    const float* Bz = g_vals + (size_t)z * WTOT * DVv;

    int tid  = threadIdx.x;
    int warp = tid >> 5, lane = tid & 31;
    int g  = lane >> 2, tg = lane & 3;
    int wm = (warp >> 1) * 32;
    int wn = (warp & 1) * 64;
    int row0 = blockIdx.y * 128;

    float c[2][8][4];
    #pragma unroll
    for (int mt = 0; mt < 2; mt++)
        #pragma unroll
        for (int nt = 0; nt < 8; nt++)
            #pragma unroll
            for (int j = 0; j < 4; j++) c[mt][nt][j] = 0.f;

    for (int k0 = 0; k0 < WTOT; k0 += 32) {
        #pragma unroll
        for (int i = 0; i < 4; i++) {
            int f = tid + i*256;
            int r = f >> 3, q4 = f & 7;
            float4 v = *(const float4*)&Az[(size_t)(row0 + r)*WTOT + k0 + q4*4];
            split2(v.x, v.y, Ah[r][2*q4],   Al[r][2*q4]);
            split2(v.z, v.w, Ah[r][2*q4+1], Al[r][2*q4+1]);
        }
        #pragma unroll
        for (int i = 0; i < 2; i++) {
            int f = tid + i*256;
            int kp = f >> 5, n4 = f & 31;
            float4 v0 = *(const float4*)&Bz[(size_t)(k0 + 2*kp    )*128 + n4*4];
            float4 v1 = *(const float4*)&Bz[(size_t)(k0 + 2*kp + 1)*128 + n4*4];
            split2(v0.x, v1.x, BhT[kp][4*n4+0], BlT[kp][4*n4+0]);
            split2(v0.y, v1.y, BhT[kp][4*n4+1], BlT[kp][4*n4+1]);
            split2(v0.z, v1.z, BhT[kp][4*n4+2], BlT[kp][4*n4+2]);
            split2(v0.w, v1.w, BhT[kp][4*n4+3], BlT[kp][4*n4+3]);
        }
        __syncthreads();
        #pragma unroll
        for (int c16 = 0; c16 < 2; c16++) {
            int coff = c16 * 8;
            uint32_t ah[2][4], al[2][4];
            #pragma unroll
            for (int mt = 0; mt < 2; mt++) {
                int m0 = wm + mt*16;
                ah[mt][0] = Ah[m0 + g    ][coff + tg    ];
                ah[mt][1] = Ah[m0 + g + 8][coff + tg    ];
                ah[mt][2] = Ah[m0 + g    ][coff + tg + 4];
                ah[mt][3] = Ah[m0 + g + 8][coff + tg + 4];
                al[mt][0] = Al[m0 + g    ][coff + tg    ];
                al[mt][1] = Al[m0 + g + 8][coff + tg    ];
                al[mt][2] = Al[m0 + g    ][coff + tg + 4];
                al[mt][3] = Al[m0 + g + 8][coff + tg + 4];
            }
            #pragma unroll
            for (int nt = 0; nt < 8; nt++) {
                int n0 = wn + nt*8 + g;
                uint32_t bh[2], bl[2];
                bh[0] = BhT[coff + tg    ][n0];
                bh[1] = BhT[coff + tg + 4][n0];
                bl[0] = BlT[coff + tg    ][n0];
                bl[1] = BlT[coff + tg + 4][n0];
                #pragma unroll
                for (int mt = 0; mt < 2; mt++) {
                    mma_bf16(c[mt][nt], ah[mt], bh);
                    mma_bf16(c[mt][nt], ah[mt], bl);
                    mma_bf16(c[mt][nt], al[mt], bh);
                }
            }
        }
        __syncthreads();
    }

    #pragma unroll
    for (int mt = 0; mt < 2; mt++) {
        int row = row0 + wm + mt*16 + g;
        #pragma unroll
        for (int nt = 0; nt < 8; nt++) {
            int col = wn + nt*8 + tg*2;
            size_t o0 = ((size_t)(b*Ll + row))*1024 + h*128 + col;
            size_t o1 = ((size_t)(b*Ll + row + 8))*1024 + h*128 + col;
            float2 g0 = *(const float2*)&g_g[o0];
            float2 g1 = *(const float2*)&g_g[o1];
            *(float2*)&g_wvg[o0] = make_float2(c[mt][nt][0]*g0.x, c[mt][nt][1]*g0.y);
            *(float2*)&g_wvg[o1] = make_float2(c[mt][nt][2]*g1.x, c[mt][nt][3]*g1.y);
        }
    }
}

// ---------------- 3a) k LN only ----------------------------------------------
__global__ void kln_kernel() {
    __shared__ float sh[4];
    int bl = blockIdx.x, h = blockIdx.y, t = threadIdx.x;
    int b = bl >> 9, l = bl & 511;
    size_t bh = (size_t)(b*Hh + h);

    float x  = g_kvg[(size_t)bl*3072 + h*128 + t];
    float mu = blockReduceSum128(x, sh) * (1.f/128.f);
    float d  = x - mu;
    float var = blockReduceSum128(d*d, sh) * (1.f/128.f);
    g_kn[(bh*Ll + l)*128 + t] = d * rsqrtf(var + 1e-6f);
}

// ---------------- 3b) q LN + qu/qv, v copy, gate -----------------------------
__global__ void qgate_kernel(const float* __restrict__ xu, const float* __restrict__ xv) {
    __shared__ float sh[4];
    int bl = blockIdx.x, h = blockIdx.y, t = threadIdx.x;
    int b = bl >> 9, l = bl & 511;
    size_t bh = (size_t)(b*Hh + h);

    float x  = g_qraw[(size_t)bl*1024 + h*128 + t];
    float mu = blockReduceSum128(x, sh) * (1.f/128.f);
    float d  = x - mu;
    float var = blockReduceSum128(d*d, sh) * (1.f/128.f);
    float qn = d * rsqrtf(var + 1e-6f);
    g_qu[(bh*Ll + l)*128 + t] = qn + xu[h*128 + t];
    g_qv[(bh*Ll + l)*128 + t] = qn + xv[h*128 + t];

    g_vals[(bh*WTOT + Mm + l)*128 + t] = g_kvg[(size_t)bl*3072 + 1024 + h*128 + t];

    float gx = g_kvg[(size_t)bl*3072 + 2048 + h*128 + t];
    g_g[(size_t)bl*1024 + h*128 + t] = gx / (1.f + __expf(-gx));
}

// ---------------- 4a) codebook squared norms ---------------------------------
__global__ void cc_kernel(const float* __restrict__ codebook) {
    int h = blockIdx.x, s = threadIdx.x;
    const float4* c = (const float4*)(codebook + ((size_t)h*Ss + s)*128);
    float acc = 0.f;
    #pragma unroll 8
    for (int i = 0; i < 32; i++) {
        float4 v = c[i];
        acc += v.x*v.x + v.y*v.y + v.z*v.z + v.w*v.w;
    }
    g_cc[h*Ss + s] = acc;
}

// ---------------- 4b) guarded argmin: approx best/2nd, exact recheck ---------
// approx scores (kn . cb^T, bf16 3-term) in g_S2[t][512]; warp per token.
__global__ void argmin_kernel(const float* __restrict__ codebook) {
    int t = blockIdx.x * 8 + (threadIdx.x >> 5);   // token = z*512 + l
    int lane = threadIdx.x & 31;
    int z = t >> 9;
    int h = z & 7;
    const float* sc = g_S2 + (size_t)t * 512;
    const float* cc = g_cc + h*512;

    float b1 = 3.4e38f, b2 = 3.4e38f; int i1 = 0x7fffffff;
    for (int s = lane; s < 512; s += 32) {
        float v = cc[s] - 2.f*sc[s];
        if (v < b1) { b2 = b1; b1 = v; i1 = s; }
        else if (v < b2) b2 = v;
    }
    #pragma unroll
    for (int o = 16; o > 0; o >>= 1) {
        float ov1 = __shfl_xor_sync(0xffffffffu, b1, o);
        int   oi1 = __shfl_xor_sync(0xffffffffu, i1, o);
        float ov2 = __shfl_xor_sync(0xffffffffu, b2, o);
        if (ov1 < b1 || (ov1 == b1 && oi1 < i1)) {
            b2 = fminf(b1, ov2);
            b1 = ov1; i1 = oi1;
        } else {
            b2 = fminf(b2, ov1);
        }
    }
    // all lanes now agree on b1, b2, i1 (xor butterfly converges)
    if (b2 - b1 < TAU_GAP) {
        // exact fp32 recheck against all 512 codes
        const float* kr = g_kn + (size_t)t * 128;
        float be = 3.4e38f; int ie = 0x7fffffff;
        for (int s = lane; s < 512; s += 32) {
            const float4* c = (const float4*)(codebook + ((size_t)h*Ss + s)*128);
            float dot = 0.f, ccv = 0.f;
            #pragma unroll 4
            for (int d4 = 0; d4 < 32; d4++) {
                float4 cv = c[d4];
                float4 kv = *(const float4*)&kr[d4*4];
                ccv += cv.x*cv.x + cv.y*cv.y + cv.z*cv.z + cv.w*cv.w;
                dot += cv.x*kv.x + cv.y*kv.y + cv.z*kv.z + cv.w*kv.w;
            }
            float v = ccv - 2.f*dot;
            if (v < be) { be = v; ie = s; }
        }
        #pragma unroll
        for (int o = 16; o > 0; o >>= 1) {
            float ov = __shfl_xor_sync(0xffffffffu, be, o);
            int   oi = __shfl_xor_sync(0xffffffffu, ie, o);
            if (ov < be || (ov == be && oi < ie)) { be = ov; ie = oi; }
        }
        i1 = ie;
    }
    if (lane == 0) g_z[t] = i1;
}

// ---------------- 5) assemble vals from inputs only --------------------------
__global__ void assembleV_kernel(const float* __restrict__ xlv,
                                 const float* __restrict__ aggU) {
    for (int e = blockIdx.x*blockDim.x + threadIdx.x; e < Bb*Hh*Mm*DKk;
         e += gridDim.x*blockDim.x) {
        int bh  = e >> 16;
        int rem = e & 65535;
        int m = rem >> 7, d = rem & 127;
        g_vals[((size_t)bh*WTOT + m)*128 + d] = xlv[e];
        g_vals[((size_t)bh*WTOT + WREC + m)*128 + d] = aggU[e];
    }
}

// ---------------- 6) softmax with fused c_z gather ---------------------------
__global__ void softmax_kernel(const float* __restrict__ aggL) {
    __shared__ float red[4];
    int l = blockIdx.x, z = blockIdx.y, tid = threadIdx.x;
    float* S1row = g_S1 + ((size_t)z*Ll + l)*WTOT;
    const float* S2row = g_S2 + ((size_t)z*Ll + l)*WREC;
    const int* zrow = g_z + (size_t)z*Ll;
    int limit = l + Mm;

    float sv[12];
    float m = -3.4e38f;
    #pragma unroll
    for (int i = 0; i < 12; i++) {
        int w = tid + i*128;
        float s;
        if (w < 512) {
            s = (S1row[w] + S2row[w + 511 - l]) * INVTAU;    // w <= 511 <= limit always
        } else if (w < WREC) {
            if (w <= limit)
                s = (S1row[1024 + zrow[w - 512]] + S2row[w + 511 - l]) * INVTAU;
            else
                s = -3.4e38f;
        } else {
            float al = aggL[(size_t)z*Ss + (w - WREC)];
            float bias = (al > 0.f) ? logf(fmaxf(al, 1e-30f)) : -1e30f;
            s = S1row[w] * INVTAU + bias;
        }
        sv[i] = s;
        m = fmaxf(m, s);
    }
    #pragma unroll
    for (int o = 16; o > 0; o >>= 1) m = fmaxf(m, __shfl_xor_sync(0xffffffffu, m, o));
    if ((tid & 31) == 0) red[tid >> 5] = m;
    __syncthreads();
    m = fmaxf(fmaxf(red[0], red[1]), fmaxf(red[2], red[3]));
    __syncthreads();

    float ssum = 0.f;
    #pragma unroll
    for (int i = 0; i < 12; i++) {
        float p = (sv[i] > -1e37f) ? __expf(sv[i] - m) : 0.f;
        sv[i] = p;
        ssum += p;
    }
    #pragma unroll
    for (int o = 16; o > 0; o >>= 1) ssum += __shfl_xor_sync(0xffffffffu, ssum, o);
    if ((tid & 31) == 0) red[tid >> 5] = ssum;
    __syncthreads();
    float invd = 1.f / (red[0] + red[1] + red[2] + red[3]);

    #pragma unroll
    for (int i = 0; i < 12; i++) S1row[tid + i*128] = sv[i] * invd;
}

// ---------------- launch ------------------------------------------------------
extern "C" void kernel_launch(void* const* d_in, const int* in_sizes, int n_in,
                              void* d_out, int out_size) {
    const float* input = (const float*)d_in[0];
    const float* xlk   = (const float*)d_in[2];
    const float* xlv   = (const float*)d_in[3];
    const float* aggU  = (const float*)d_in[4];
    const float* aggL  = (const float*)d_in[5];
    const float* Wq    = (const float*)d_in[6];
    const float* Wkvg  = (const float*)d_in[7];
    const float* Wres  = (const float*)d_in[8];
    const float* xu    = (const float*)d_in[9];
    const float* xv    = (const float*)d_in[10];
    const float* xlr   = (const float*)d_in[11];
    const float* cb    = (const float*)d_in[12];
    float* out = (float*)d_out;

    float *xt, *qraw, *kvg, *wvg, *qu, *qv, *S1, *S2, *kn;
    cudaGetSymbolAddress((void**)&xt,   g_xt);
    cudaGetSymbolAddress((void**)&qraw, g_qraw);
    cudaGetSymbolAddress((void**)&kvg,  g_kvg);
    cudaGetSymbolAddress((void**)&wvg,  g_wvg);
    cudaGetSymbolAddress((void**)&qu,   g_qu);
    cudaGetSymbolAddress((void**)&qv,   g_qv);
    cudaGetSymbolAddress((void**)&S1,   g_S1);
    cudaGetSymbolAddress((void**)&S2,   g_S2);
    cudaGetSymbolAddress((void**)&kn,   g_kn);

    const int TF32_SMEM = (2*128*36 + 2*32*132) * 4;   // 70656
    cudaFuncSetAttribute(gemm_tf32_kernel,
                         cudaFuncAttributeMaxDynamicSharedMemorySize, TF32_SMEM);

    // ---- prep ----
    assembleV_kernel<<<2048, 256>>>(xlv, aggU);
    ln_input_kernel<<<Bb*Ll, 256>>>(input);

    // ---- projections ----
    gemm_ffma_kernel<<<dim3(8, 32), 256>>>(xt, Wkvg, kvg, 4096, 3072, 1024);   // k cols fp32
    gemm_tf32_kernel<<<dim3(8, 32), 256, TF32_SMEM>>>(xt, Wq, qraw, 4096, 1024, 1024);
    gemm_tf32_kernel<<<dim3(16, 32), 256, TF32_SMEM>>>(xt, Wkvg + 1024, kvg + 1024,
                                                       4096, 3072, 1024);
    kln_kernel<<<dim3(Bb*Ll, Hh), 128>>>();
    qgate_kernel<<<dim3(Bb*Ll, Hh), 128>>>(xu, xv);

    // ---- VQ: bf16 tensor scores + guarded argmin ----
    cc_kernel<<<Hh, Ss>>>(cb);
    gemm_ntbf_kernel<<<dim3(4, 4, 64), 256>>>(
        kn, cb, S2,
        (size_t)Ll*128, (size_t)Ss*128, (size_t)Ll*Ss, 1, Ss, 0);
    argmin_kernel<<<Bb*Hh*Ll/8, 256>>>(cb);

    // ---- attention scores (all z-free; c_z block gathered in softmax) ----
    gemm_ntbf_kernel<<<dim3(WREC/128, Ll/128, 64), 256>>>(     // S2 = qv @ xlr^T
        qv, xlr, S2,
        (size_t)Ll*128, (size_t)WREC*128, (size_t)Ll*WREC, 1, WREC, 0);
    gemm_ntbf_kernel<<<dim3(4, 4, 64), 256>>>(                 // S1 xlk cols [0,512)
        qu, xlk, S1,
        (size_t)Ll*128, (size_t)Mm*128, (size_t)Ll*WTOT, 0, WTOT, 0);
    gemm_ntbf_kernel<<<dim3(4, 4, 64), 256>>>(                 // S1 cb cols [1024,1536)
        qu, cb, S1,
        (size_t)Ll*128, (size_t)Ss*128, (size_t)Ll*WTOT, 1, WTOT, 1024);

    softmax_kernel<<<dim3(Ll, 64), 128>>>(aggL);
    gemm_valbf_kernel<<<dim3(1, Ll/128, 64), 256>>>();
    gemm_tf32_kernel<<<dim3(8, 32), 256, TF32_SMEM>>>(wvg, Wres, out, 4096, 1024, 1024);
}

// round 12
// speedup vs baseline: 1.1253x; 1.0112x over previous
#include <cuda_runtime.h>
#include <cuda_bf16.h>
#include <math.h>
#include <stdint.h>

// Shapes (fixed for this problem)
#define Bb   8
#define Ll   512
#define Mm   512
#define Hh   8
#define DKk  128
#define DVv  128
#define Ss   512
#define DMm  1024
#define WREC 1024
#define WTOT 1536    // recent 1024 + cache 512

#define INVTAU 0.08838834764831845f   // 1/sqrt(128)
#define TAU_GAP 0.01f

// ---------------- scratch (device globals; no allocation allowed) ------------
__device__ float g_xt  [Bb*Ll*DMm];
__device__ float g_qraw[Bb*Ll*Hh*DKk];
__device__ float g_kvg [Bb*Ll*3072];
__device__ float g_kn  [Bb*Hh*Ll*DKk];        // fp32 kn for exact argmin recheck
__device__ float g_g   [Bb*Ll*Hh*DVv];
__device__ float g_vmid[64*Ll*DVv];           // current v (pre-pair scratch)
__device__ float g_S1  [(size_t)64*Ll*WTOT];  // raw scores
__device__ float g_S2  [(size_t)64*Ll*WREC];  // VQ scores scratch, then BD term
__device__ float g_wvg [Bb*Ll*Hh*DVv];
__device__ float g_cc  [Hh*Ss];
__device__ int   g_z   [Bb*Hh*Ll];

// pre-split bf16 (hi,lo) pair arrays: pair couples k (or w) elements 2j,2j+1
__device__ uint32_t g_quh[64*Ll*64],  g_qul[64*Ll*64];
__device__ uint32_t g_qvh[64*Ll*64],  g_qvl[64*Ll*64];
__device__ uint32_t g_knh[64*Ll*64],  g_knl[64*Ll*64];
__device__ uint32_t g_xkh[64*Ll*64],  g_xkl[64*Ll*64];   // xl_k_hat
__device__ uint32_t g_cbh[Hh*Ss*64],  g_cbl[Hh*Ss*64];   // codebook
__device__ uint32_t g_xrh[Hh*WREC*64],g_xrl[Hh*WREC*64]; // xl_r
__device__ uint32_t g_vh [(size_t)64*768*128], g_vl [(size_t)64*768*128]; // vals (w-pairs)
__device__ uint32_t g_Ph [(size_t)64*Ll*768],  g_Pl [(size_t)64*Ll*768]; // probs (w-pairs)

// ---------------- helpers ----------------------------------------------------
__device__ __forceinline__ uint32_t tf32_of(float x) {
    uint32_t u;
    asm("cvt.rna.tf32.f32 %0, %1;" : "=r"(u) : "f"(x));
    return u;
}

__device__ __forceinline__ uint32_t smem_u32(const void* p) {
    return (uint32_t)__cvta_generic_to_shared(p);
}
#define CP_ASYNC16(dst, src) \
    asm volatile("cp.async.cg.shared.global [%0], [%1], 16;" :: "r"(dst), "l"(src))
#define CP_COMMIT() asm volatile("cp.async.commit_group;")
#define CP_WAIT1()  asm volatile("cp.async.wait_group 1;")
#define CP_WAIT0()  asm volatile("cp.async.wait_group 0;")

__device__ __forceinline__ void mma_tf32(float* c, const uint32_t* a, const uint32_t* b) {
    asm volatile(
        "mma.sync.aligned.m16n8k8.row.col.f32.tf32.tf32.f32 "
        "{%0,%1,%2,%3}, {%4,%5,%6,%7}, {%8,%9}, {%0,%1,%2,%3};"
        : "+f"(c[0]), "+f"(c[1]), "+f"(c[2]), "+f"(c[3])
        : "r"(a[0]), "r"(a[1]), "r"(a[2]), "r"(a[3]), "r"(b[0]), "r"(b[1]));
}

__device__ __forceinline__ void mma_bf16(float* c, const uint32_t* a, const uint32_t* b) {
    asm volatile(
        "mma.sync.aligned.m16n8k16.row.col.f32.bf16.bf16.f32 "
        "{%0,%1,%2,%3}, {%4,%5,%6,%7}, {%8,%9}, {%0,%1,%2,%3};"
        : "+f"(c[0]), "+f"(c[1]), "+f"(c[2]), "+f"(c[3])
        : "r"(a[0]), "r"(a[1]), "r"(a[2]), "r"(a[3]), "r"(b[0]), "r"(b[1]));
}

// split two floats into packed bf16x2 hi and lo words (pair: x->low, y->high)
__device__ __forceinline__ void split2(float x, float y, uint32_t& hi, uint32_t& lo) {
    __nv_bfloat162 h = __floats2bfloat162_rn(x, y);
    float hx = __bfloat162float(h.x), hy = __bfloat162float(h.y);
    __nv_bfloat162 l = __floats2bfloat162_rn(x - hx, y - hy);
    hi = *(uint32_t*)&h;
    lo = *(uint32_t*)&l;
}

__device__ __forceinline__ float blockReduceSum256(float v, float* sh) {
    #pragma unroll
    for (int o = 16; o > 0; o >>= 1) v += __shfl_xor_sync(0xffffffffu, v, o);
    __syncthreads();
    if ((threadIdx.x & 31) == 0) sh[threadIdx.x >> 5] = v;
    __syncthreads();
    float r = 0.f;
    #pragma unroll
    for (int i = 0; i < 8; i++) r += sh[i];
    return r;
}

__device__ __forceinline__ float blockReduceSum128(float v, float* sh) {
    #pragma unroll
    for (int o = 16; o > 0; o >>= 1) v += __shfl_xor_sync(0xffffffffu, v, o);
    __syncthreads();
    if ((threadIdx.x & 31) == 0) sh[threadIdx.x >> 5] = v;
    __syncthreads();
    return sh[0] + sh[1] + sh[2] + sh[3];
}

// ---------------- 0a) generic pre-split (pairs along contiguous k) -----------
__global__ void convA_kernel(const float* __restrict__ src, uint32_t* __restrict__ dh,
                             uint32_t* __restrict__ dl, int totalPairs) {
    int i = blockIdx.x*256 + threadIdx.x;
    if (i >= totalPairs) return;
    float2 v = *(const float2*)&src[2*i];
    uint32_t hi, lo; split2(v.x, v.y, hi, lo);
    dh[i] = hi; dl[i] = lo;
}

// ---------------- 0b) vals assembly (pairs across w rows) --------------------
__global__ void assembleV_kernel(const float* __restrict__ xlv,
                                 const float* __restrict__ aggU) {
    int idx = blockIdx.x*256 + threadIdx.x;   // 64*256*128 = 2M
    int d = idx & 127; int rest = idx >> 7;
    int ip = rest & 255; int bh = rest >> 8;
    size_t si = ((size_t)bh*512 + 2*ip)*128 + d;
    uint32_t hi, lo;
    split2(xlv[si], xlv[si + 128], hi, lo);
    size_t o = ((size_t)bh*768 + ip)*128 + d;
    g_vh[o] = hi; g_vl[o] = lo;
    split2(aggU[si], aggU[si + 128], hi, lo);
    o = ((size_t)bh*768 + 512 + ip)*128 + d;
    g_vh[o] = hi; g_vl[o] = lo;
}

// current v rows (g_vmid) -> vals pairs 256..511
__global__ void convV_kernel() {
    int idx = blockIdx.x*256 + threadIdx.x;   // 2M
    int d = idx & 127; int rest = idx >> 7;
    int ip = rest & 255; int bh = rest >> 8;
    float a = g_vmid[((size_t)bh*512 + 2*ip)*128 + d];
    float b = g_vmid[((size_t)bh*512 + 2*ip + 1)*128 + d];
    uint32_t hi, lo; split2(a, b, hi, lo);
    size_t o = ((size_t)bh*768 + 256 + ip)*128 + d;
    g_vh[o] = hi; g_vl[o] = lo;
}

// ---------------- 1) LayerNorm of input (rows of 1024) -----------------------
__global__ void ln_input_kernel(const float* __restrict__ x) {
    __shared__ float sh[8];
    size_t base = (size_t)blockIdx.x * DMm;
    float lv[4]; float s = 0.f;
    #pragma unroll
    for (int j = 0; j < 4; j++) { lv[j] = x[base + threadIdx.x + j*256]; s += lv[j]; }
    float mu = blockReduceSum256(s, sh) * (1.f/1024.f);
    float s2 = 0.f;
    #pragma unroll
    for (int j = 0; j < 4; j++) { float d = lv[j] - mu; s2 += d*d; }
    float var = blockReduceSum256(s2, sh) * (1.f/1024.f);
    float rstd = rsqrtf(var + 1e-6f);
    #pragma unroll
    for (int j = 0; j < 4; j++) g_xt[base + threadIdx.x + j*256] = (lv[j]-mu)*rstd;
}

// ---------------- 2a) fp32 FFMA GEMM (full precision, k-columns) -------------
__global__ void __launch_bounds__(256, 2)
gemm_ffma_kernel(const float* __restrict__ A, const float* __restrict__ B,
                 float* __restrict__ C, int M, int N, int K) {
    __shared__ float As[16][132];
    __shared__ float Bs[16][132];
    int tid  = threadIdx.x;
    int row0 = blockIdx.y * 128;
    int col0 = blockIdx.x * 128;
    int tx = tid & 15, ty = tid >> 4;

    float acc[8][8];
    #pragma unroll
    for (int i = 0; i < 8; i++)
        #pragma unroll
        for (int j = 0; j < 8; j++) acc[i][j] = 0.f;

    for (int k0 = 0; k0 < K; k0 += 16) {
        #pragma unroll
        for (int i = 0; i < 2; i++) {
            int f = tid + i*256;
            int r = f >> 2, c4 = f & 3;
            float4 v = *(const float4*)&A[(size_t)(row0 + r)*K + k0 + c4*4];
            As[c4*4+0][r] = v.x; As[c4*4+1][r] = v.y;
            As[c4*4+2][r] = v.z; As[c4*4+3][r] = v.w;
        }
        #pragma unroll
        for (int i = 0; i < 2; i++) {
            int f = tid + i*256;
            int r = f >> 5, c4 = f & 31;
            *(float4*)&Bs[r][c4*4] = *(const float4*)&B[(size_t)(k0 + r)*N + col0 + c4*4];
        }
        __syncthreads();
        #pragma unroll
        for (int kk = 0; kk < 16; kk++) {
            float a[8], bb[8];
            *(float4*)&a[0]  = *(float4*)&As[kk][ty*8];
            *(float4*)&a[4]  = *(float4*)&As[kk][ty*8 + 4];
            *(float4*)&bb[0] = *(float4*)&Bs[kk][tx*4];
            *(float4*)&bb[4] = *(float4*)&Bs[kk][64 + tx*4];
            #pragma unroll
            for (int i = 0; i < 8; i++)
                #pragma unroll
                for (int j = 0; j < 8; j++) acc[i][j] += a[i]*bb[j];
        }
        __syncthreads();
    }
    #pragma unroll
    for (int i = 0; i < 8; i++) {
        size_t crow = (size_t)(row0 + ty*8 + i)*N;
        *(float4*)&C[crow + col0 + tx*4]      = make_float4(acc[i][0], acc[i][1], acc[i][2], acc[i][3]);
        *(float4*)&C[crow + col0 + 64 + tx*4] = make_float4(acc[i][4], acc[i][5], acc[i][6], acc[i][7]);
    }
}

// ---------------- 2b) tf32 1-term GEMM, cp.async double-buffered -------------
__global__ void __launch_bounds__(256, 2)
gemm_tf32_kernel(const float* __restrict__ A, const float* __restrict__ B,
                 float* __restrict__ C, int M, int N, int K) {
    extern __shared__ float sm[];
    const int ASZ = 128*36, BSZ = 32*132;
    int tid  = threadIdx.x;
    int warp = tid >> 5, lane = tid & 31;
    int g  = lane >> 2, tg = lane & 3;
    int wm = (warp >> 1) * 32;
    int wn = (warp & 1) * 64;
    int row0 = blockIdx.y * 128;
    int col0 = blockIdx.x * 128;

    float c[2][8][4];
    #pragma unroll
    for (int mt = 0; mt < 2; mt++)
        #pragma unroll
        for (int nt = 0; nt < 8; nt++)
            #pragma unroll
            for (int j = 0; j < 4; j++) c[mt][nt][j] = 0.f;

    #define STAGE(k0_, buf_) do {                                              \
        float* As_ = sm + (buf_)*ASZ;                                          \
        float* Bs_ = sm + 2*ASZ + (buf_)*BSZ;                                  \
        _Pragma("unroll")                                                      \
        for (int i_ = 0; i_ < 4; i_++) {                                       \
            int f_ = tid + i_*256;                                             \
            int r_ = f_ >> 3, c4_ = (f_ & 7) * 4;                              \
            CP_ASYNC16(smem_u32(&As_[r_*36 + c4_]),                            \
                       &A[(size_t)(row0 + r_)*K + (k0_) + c4_]);               \
        }                                                                      \
        _Pragma("unroll")                                                      \
        for (int i_ = 0; i_ < 4; i_++) {                                       \
            int f_ = tid + i_*256;                                             \
            int r_ = f_ >> 5, c4_ = (f_ & 31) * 4;                             \
            CP_ASYNC16(smem_u32(&Bs_[r_*132 + c4_]),                           \
                       &B[(size_t)((k0_) + r_)*N + col0 + c4_]);               \
        }                                                                      \
    } while (0)

    STAGE(0, 0); CP_COMMIT();

    for (int k0 = 0; k0 < K; k0 += 32) {
        int buf = (k0 >> 5) & 1;
        if (k0 + 32 < K) { STAGE(k0 + 32, buf ^ 1); CP_COMMIT(); CP_WAIT1(); }
        else             { CP_WAIT0(); }
        __syncthreads();
        float* As = sm + buf*ASZ;
        float* Bs = sm + 2*ASZ + buf*BSZ;
        #pragma unroll
        for (int ks = 0; ks < 4; ks++) {
            int kk = ks * 8;
            uint32_t a[2][4], b[8][2];
            #pragma unroll
            for (int mt = 0; mt < 2; mt++) {
                int m0 = wm + mt*16;
                a[mt][0] = tf32_of(As[(m0 + g    )*36 + kk + tg    ]);
                a[mt][1] = tf32_of(As[(m0 + g + 8)*36 + kk + tg    ]);
                a[mt][2] = tf32_of(As[(m0 + g    )*36 + kk + tg + 4]);
                a[mt][3] = tf32_of(As[(m0 + g + 8)*36 + kk + tg + 4]);
            }
            #pragma unroll
            for (int nt = 0; nt < 8; nt++) {
                int n0 = wn + nt*8 + g;
                b[nt][0] = tf32_of(Bs[(kk + tg    )*132 + n0]);
                b[nt][1] = tf32_of(Bs[(kk + tg + 4)*132 + n0]);
            }
            #pragma unroll
            for (int mt = 0; mt < 2; mt++)
                #pragma unroll
                for (int nt = 0; nt < 8; nt++)
                    mma_tf32(c[mt][nt], a[mt], b[nt]);
        }
        __syncthreads();
    }
    #undef STAGE

    #pragma unroll
    for (int mt = 0; mt < 2; mt++) {
        int row = row0 + wm + mt*16 + g;
        #pragma unroll
        for (int nt = 0; nt < 8; nt++) {
            int col = col0 + wn + nt*8 + tg*2;
            *(float2*)&C[(size_t)row*N + col]     = make_float2(c[mt][nt][0], c[mt][nt][1]);
            *(float2*)&C[(size_t)(row+8)*N + col] = make_float2(c[mt][nt][2], c[mt][nt][3]);
        }
    }
}

// ---------------- 2c) batched NT bf16 3-term GEMM on pre-split operands ------
__global__ void __launch_bounds__(256, 2)
gemm_ntbf_kernel(const uint32_t* __restrict__ Ahg, const uint32_t* __restrict__ Alg,
                 const uint32_t* __restrict__ Bhg, const uint32_t* __restrict__ Blg,
                 float* __restrict__ C,
                 size_t strideA, size_t strideB, size_t strideC,
                 int bPerHead, int ldC, int colOff, int skipThresh) {
    __shared__ uint32_t Ah[128][20], Al[128][20], Bh[128][20], Bl[128][20];

    int row0 = blockIdx.y * 128;
    int col0 = blockIdx.x * 128;
    if (col0 + 128 <= skipThresh - row0) return;   // masked-out S2 tiles

    int z = blockIdx.z;
    const uint32_t* Azh = Ahg + (size_t)z * strideA;
    const uint32_t* Azl = Alg + (size_t)z * strideA;
    size_t bo = (size_t)(bPerHead ? (z & 7) : z) * strideB;
    const uint32_t* Bzh = Bhg + bo;
    const uint32_t* Bzl = Blg + bo;
    float* Cz = C + (size_t)z * strideC;

    int tid  = threadIdx.x;
    int warp = tid >> 5, lane = tid & 31;
    int g  = lane >> 2, tg = lane & 3;
    int wm = (warp >> 1) * 32;
    int wn = (warp & 1) * 64;

    float c[2][8][4];
    #pragma unroll
    for (int mt = 0; mt < 2; mt++)
        #pragma unroll
        for (int nt = 0; nt < 8; nt++)
            #pragma unroll
            for (int j = 0; j < 4; j++) c[mt][nt][j] = 0.f;

    for (int kp0 = 0; kp0 < 64; kp0 += 16) {
        #pragma unroll
        for (int i = 0; i < 2; i++) {
            int f = tid + i*256;
            int r = f >> 2, q4 = (f & 3) * 4;
            *(uint4*)&Ah[r][q4] = *(const uint4*)&Azh[(size_t)(row0 + r)*64 + kp0 + q4];
            *(uint4*)&Al[r][q4] = *(const uint4*)&Azl[(size_t)(row0 + r)*64 + kp0 + q4];
            *(uint4*)&Bh[r][q4] = *(const uint4*)&Bzh[(size_t)(col0 + r)*64 + kp0 + q4];
            *(uint4*)&Bl[r][q4] = *(const uint4*)&Bzl[(size_t)(col0 + r)*64 + kp0 + q4];
        }
        __syncthreads();
        #pragma unroll
        for (int c16 = 0; c16 < 2; c16++) {
            int coff = c16 * 8;
            uint32_t ah[2][4], al[2][4];
            #pragma unroll
            for (int mt = 0; mt < 2; mt++) {
                int m0 = wm + mt*16;
                ah[mt][0] = Ah[m0 + g    ][coff + tg    ];
                ah[mt][1] = Ah[m0 + g + 8][coff + tg    ];
                ah[mt][2] = Ah[m0 + g    ][coff + tg + 4];
                ah[mt][3] = Ah[m0 + g + 8][coff + tg + 4];
                al[mt][0] = Al[m0 + g    ][coff + tg    ];
                al[mt][1] = Al[m0 + g + 8][coff + tg    ];
                al[mt][2] = Al[m0 + g    ][coff + tg + 4];
                al[mt][3] = Al[m0 + g + 8][coff + tg + 4];
            }
            #pragma unroll
            for (int nt = 0; nt < 8; nt++) {
                int n0 = wn + nt*8 + g;
                uint32_t bh[2], bl[2];
                bh[0] = Bh[n0][coff + tg    ];
                bh[1] = Bh[n0][coff + tg + 4];
                bl[0] = Bl[n0][coff + tg    ];
                bl[1] = Bl[n0][coff + tg + 4];
                #pragma unroll
                for (int mt = 0; mt < 2; mt++) {
                    mma_bf16(c[mt][nt], ah[mt], bh);
                    mma_bf16(c[mt][nt], ah[mt], bl);
                    mma_bf16(c[mt][nt], al[mt], bh);
                }
            }
        }
        __syncthreads();
    }

    #pragma unroll
    for (int mt = 0; mt < 2; mt++) {
        int row = row0 + wm + mt*16 + g;
        #pragma unroll
        for (int nt = 0; nt < 8; nt++) {
            int col = colOff + col0 + wn + nt*8 + tg*2;
            *(float2*)&Cz[(size_t)row*ldC + col]     = make_float2(c[mt][nt][0], c[mt][nt][1]);
            *(float2*)&Cz[(size_t)(row+8)*ldC + col] = make_float2(c[mt][nt][2], c[mt][nt][3]);
        }
    }
}

// ---------------- 2d) value GEMM on pre-split P and vals, gated epilogue -----
__global__ void __launch_bounds__(256, 2)
gemm_valbf_kernel() {
    __shared__ uint32_t Ah[128][20], Al[128][20];
    __shared__ uint32_t BhT[16][136], BlT[16][136];

    int z = blockIdx.z;
    int b = z >> 3, h = z & 7;
    const uint32_t* Azh = g_Ph + (size_t)z * Ll * 768;
    const uint32_t* Azl = g_Pl + (size_t)z * Ll * 768;
    const uint32_t* Bzh = g_vh + (size_t)z * 768 * 128;
    const uint32_t* Bzl = g_vl + (size_t)z * 768 * 128;

    int tid  = threadIdx.x;
    int warp = tid >> 5, lane = tid & 31;
    int g  = lane >> 2, tg = lane & 3;
    int wm = (warp >> 1) * 32;
    int wn = (warp & 1) * 64;
    int row0 = blockIdx.y * 128;

    float c[2][8][4];
    #pragma unroll
    for (int mt = 0; mt < 2; mt++)
        #pragma unroll
        for (int nt = 0; nt < 8; nt++)
            #pragma unroll
            for (int j = 0; j < 4; j++) c[mt][nt][j] = 0.f;

    for (int kp0 = 0; kp0 < 768; kp0 += 16) {
        int k0 = kp0 * 2;
        if (k0 >= row0 + 640 && k0 + 32 <= 1024) continue;   // causal-masked zero block
        #pragma unroll
        for (int i = 0; i < 2; i++) {
            int f = tid + i*256;
            int r = f >> 2, q4 = (f & 3) * 4;
            *(uint4*)&Ah[r][q4] = *(const uint4*)&Azh[(size_t)(row0 + r)*768 + kp0 + q4];
            *(uint4*)&Al[r][q4] = *(const uint4*)&Azl[(size_t)(row0 + r)*768 + kp0 + q4];
        }
        #pragma unroll
        for (int i = 0; i < 2; i++) {
            int f = tid + i*256;
            int kp = f >> 5, n4 = (f & 31) * 4;
            *(uint4*)&BhT[kp][n4] = *(const uint4*)&Bzh[(size_t)(kp0 + kp)*128 + n4];
            *(uint4*)&BlT[kp][n4] = *(const uint4*)&Bzl[(size_t)(kp0 + kp)*128 + n4];
        }
        __syncthreads();
        #pragma unroll
        for (int c16 = 0; c16 < 2; c16++) {
            int coff = c16 * 8;
            uint32_t ah[2][4], al[2][4];
            #pragma unroll
            for (int mt = 0; mt < 2; mt++) {
                int m0 = wm + mt*16;
                ah[mt][0] = Ah[m0 + g    ][coff + tg    ];
                ah[mt][1] = Ah[m0 + g + 8][coff + tg    ];
                ah[mt][2] = Ah[m0 + g    ][coff + tg + 4];
                ah[mt][3] = Ah[m0 + g + 8][coff + tg + 4];
                al[mt][0] = Al[m0 + g    ][coff + tg    ];
                al[mt][1] = Al[m0 + g + 8][coff + tg    ];
                al[mt][2] = Al[m0 + g    ][coff + tg + 4];
                al[mt][3] = Al[m0 + g + 8][coff + tg + 4];
            }
            #pragma unroll
            for (int nt = 0; nt < 8; nt++) {
                int n0 = wn + nt*8 + g;
                uint32_t bh[2], bl[2];
                bh[0] = BhT[coff + tg    ][n0];
                bh[1] = BhT[coff + tg + 4][n0];
                bl[0] = BlT[coff + tg    ][n0];
                bl[1] = BlT[coff + tg + 4][n0];
                #pragma unroll
                for (int mt = 0; mt < 2; mt++) {
                    mma_bf16(c[mt][nt], ah[mt], bh);
                    mma_bf16(c[mt][nt], ah[mt], bl);
                    mma_bf16(c[mt][nt], al[mt], bh);
                }
            }
        }
        __syncthreads();
    }

    #pragma unroll
    for (int mt = 0; mt < 2; mt++) {
        int row = row0 + wm + mt*16 + g;
        #pragma unroll
        for (int nt = 0; nt < 8; nt++) {
            int col = wn + nt*8 + tg*2;
            size_t o0 = ((size_t)(b*Ll + row))*1024 + h*128 + col;
            size_t o1 = ((size_t)(b*Ll + row + 8))*1024 + h*128 + col;
            float2 g0 = *(const float2*)&g_g[o0];
            float2 g1 = *(const float2*)&g_g[o1];
            *(float2*)&g_wvg[o0] = make_float2(c[mt][nt][0]*g0.x, c[mt][nt][1]*g0.y);
            *(float2*)&g_wvg[o1] = make_float2(c[mt][nt][2]*g1.x, c[mt][nt][3]*g1.y);
        }
    }
}

// ---------------- 3a) k LN + pre-split kn ------------------------------------
__global__ void kln_kernel() {
    __shared__ float sh[4];
    int bl = blockIdx.x, h = blockIdx.y, t = threadIdx.x;
    int b = bl >> 9, l = bl & 511;
    size_t bh = (size_t)(b*Hh + h);

    float x  = g_kvg[(size_t)bl*3072 + h*128 + t];
    float mu = blockReduceSum128(x, sh) * (1.f/128.f);
    float d  = x - mu;
    float var = blockReduceSum128(d*d, sh) * (1.f/128.f);
    float kn = d * rsqrtf(var + 1e-6f);
    g_kn[(bh*Ll + l)*128 + t] = kn;

    float knp = __shfl_down_sync(0xffffffffu, kn, 1);
    if ((t & 1) == 0) {
        uint32_t hi, lo; split2(kn, knp, hi, lo);
        size_t o = (bh*Ll + l)*64 + (t >> 1);
        g_knh[o] = hi; g_knl[o] = lo;
    }
}

// ---------------- 3b) q LN + qu/qv pre-split, v copy, gate -------------------
__global__ void qgate_kernel(const float* __restrict__ xu, const float* __restrict__ xv) {
    __shared__ float sh[4];
    int bl = blockIdx.x, h = blockIdx.y, t = threadIdx.x;
    int b = bl >> 9, l = bl & 511;
    size_t bh = (size_t)(b*Hh + h);

    float x  = g_qraw[(size_t)bl*1024 + h*128 + t];
    float mu = blockReduceSum128(x, sh) * (1.f/128.f);
    float d  = x - mu;
    float var = blockReduceSum128(d*d, sh) * (1.f/128.f);
    float qn = d * rsqrtf(var + 1e-6f);
    float quv = qn + xu[h*128 + t];
    float qvv = qn + xv[h*128 + t];

    float qup = __shfl_down_sync(0xffffffffu, quv, 1);
    float qvp = __shfl_down_sync(0xffffffffu, qvv, 1);
    if ((t & 1) == 0) {
        size_t o = (bh*Ll + l)*64 + (t >> 1);
        uint32_t hi, lo;
        split2(quv, qup, hi, lo); g_quh[o] = hi; g_qul[o] = lo;
        split2(qvv, qvp, hi, lo); g_qvh[o] = hi; g_qvl[o] = lo;
    }

    g_vmid[(bh*Ll + l)*128 + t] = g_kvg[(size_t)bl*3072 + 1024 + h*128 + t];

    float gx = g_kvg[(size_t)bl*3072 + 2048 + h*128 + t];
    g_g[(size_t)bl*1024 + h*128 + t] = gx / (1.f + __expf(-gx));
}

// ---------------- 4a) codebook squared norms ---------------------------------
__global__ void cc_kernel(const float* __restrict__ codebook) {
    int h = blockIdx.x, s = threadIdx.x;
    const float4* c = (const float4*)(codebook + ((size_t)h*Ss + s)*128);
    float acc = 0.f;
    #pragma unroll 8
    for (int i = 0; i < 32; i++) {
        float4 v = c[i];
        acc += v.x*v.x + v.y*v.y + v.z*v.z + v.w*v.w;
    }
    g_cc[h*Ss + s] = acc;
}

// ---------------- 4b) guarded argmin: approx best/2nd, exact recheck ---------
__global__ void argmin_kernel(const float* __restrict__ codebook) {
    int t = blockIdx.x * 8 + (threadIdx.x >> 5);
    int lane = threadIdx.x & 31;
    int z = t >> 9;
    int h = z & 7;
    const float* sc = g_S2 + (size_t)t * 512;
    const float* cc = g_cc + h*512;

    float b1 = 3.4e38f, b2 = 3.4e38f; int i1 = 0x7fffffff;
    for (int s = lane; s < 512; s += 32) {
        float v = cc[s] - 2.f*sc[s];
        if (v < b1) { b2 = b1; b1 = v; i1 = s; }
        else if (v < b2) b2 = v;
    }
    #pragma unroll
    for (int o = 16; o > 0; o >>= 1) {
        float ov1 = __shfl_xor_sync(0xffffffffu, b1, o);
        int   oi1 = __shfl_xor_sync(0xffffffffu, i1, o);
        float ov2 = __shfl_xor_sync(0xffffffffu, b2, o);
        if (ov1 < b1 || (ov1 == b1 && oi1 < i1)) {
            b2 = fminf(b1, ov2);
            b1 = ov1; i1 = oi1;
        } else {
            b2 = fminf(b2, ov1);
        }
    }
    if (b2 - b1 < TAU_GAP) {
        const float* kr = g_kn + (size_t)t * 128;
        float be = 3.4e38f; int ie = 0x7fffffff;
        for (int s = lane; s < 512; s += 32) {
            const float4* c = (const float4*)(codebook + ((size_t)h*Ss + s)*128);
            float dot = 0.f, ccv = 0.f;
            #pragma unroll 4
            for (int d4 = 0; d4 < 32; d4++) {
                float4 cv = c[d4];
                float4 kv = *(const float4*)&kr[d4*4];
                ccv += cv.x*cv.x + cv.y*cv.y + cv.z*cv.z + cv.w*cv.w;
                dot += cv.x*kv.x + cv.y*kv.y + cv.z*kv.z + cv.w*kv.w;
            }
            float v = ccv - 2.f*dot;
            if (v < be) { be = v; ie = s; }
        }
        #pragma unroll
        for (int o = 16; o > 0; o >>= 1) {
            float ov = __shfl_xor_sync(0xffffffffu, be, o);
            int   oi = __shfl_xor_sync(0xffffffffu, ie, o);
            if (ov < be || (ov == be && oi < ie)) { be = ov; ie = oi; }
        }
        i1 = ie;
    }
    if (lane == 0) g_z[t] = i1;
}

// ---------------- 6) softmax with fused c_z gather; emits pre-split probs ----
__global__ void softmax_kernel(const float* __restrict__ aggL) {
    __shared__ float red[4];
    int l = blockIdx.x, z = blockIdx.y, tid = threadIdx.x;
    const float* S1row = g_S1 + ((size_t)z*Ll + l)*WTOT;
    const float* S2row = g_S2 + ((size_t)z*Ll + l)*WREC;
    const int* zrow = g_z + (size_t)z*Ll;
    int limit = l + Mm;

    float pv[12];
    float m = -3.4e38f;
    #pragma unroll
    for (int i = 0; i < 6; i++) {
        int p = tid + i*128;
        #pragma unroll
        for (int u = 0; u < 2; u++) {
            int w = 2*p + u;
            float s;
            if (w < 512) {
                s = (S1row[w] + S2row[w + 511 - l]) * INVTAU;
            } else if (w < WREC) {
                if (w <= limit)
                    s = (S1row[1024 + zrow[w - 512]] + S2row[w + 511 - l]) * INVTAU;
                else
                    s = -3.4e38f;
            } else {
                float al = aggL[(size_t)z*Ss + (w - WREC)];
                float bias = (al > 0.f) ? logf(fmaxf(al, 1e-30f)) : -1e30f;
                s = S1row[w] * INVTAU + bias;
            }
            pv[2*i+u] = s;
            m = fmaxf(m, s);
        }
    }
    #pragma unroll
    for (int o = 16; o > 0; o >>= 1) m = fmaxf(m, __shfl_xor_sync(0xffffffffu, m, o));
    if ((tid & 31) == 0) red[tid >> 5] = m;
    __syncthreads();
    m = fmaxf(fmaxf(red[0], red[1]), fmaxf(red[2], red[3]));
    __syncthreads();

    float ssum = 0.f;
    #pragma unroll
    for (int i = 0; i < 12; i++) {
        float p = (pv[i] > -1e37f) ? __expf(pv[i] - m) : 0.f;
        pv[i] = p;
        ssum += p;
    }
    #pragma unroll
    for (int o = 16; o > 0; o >>= 1) ssum += __shfl_xor_sync(0xffffffffu, ssum, o);
    if ((tid & 31) == 0) red[tid >> 5] = ssum;
    __syncthreads();
    float invd = 1.f / (red[0] + red[1] + red[2] + red[3]);

    size_t base = ((size_t)z*Ll + l)*768;
    #pragma unroll
    for (int i = 0; i < 6; i++) {
        int p = tid + i*128;
        uint32_t hi, lo;
        split2(pv[2*i]*invd, pv[2*i+1]*invd, hi, lo);
        g_Ph[base + p] = hi;
        g_Pl[base + p] = lo;
    }
}

// ---------------- launch ------------------------------------------------------
extern "C" void kernel_launch(void* const* d_in, const int* in_sizes, int n_in,
                              void* d_out, int out_size) {
    const float* input = (const float*)d_in[0];
    const float* xlk   = (const float*)d_in[2];
    const float* xlv   = (const float*)d_in[3];
    const float* aggU  = (const float*)d_in[4];
    const float* aggL  = (const float*)d_in[5];
    const float* Wq    = (const float*)d_in[6];
    const float* Wkvg  = (const float*)d_in[7];
    const float* Wres  = (const float*)d_in[8];
    const float* xu    = (const float*)d_in[9];
    const float* xv    = (const float*)d_in[10];
    const float* xlr   = (const float*)d_in[11];
    const float* cb    = (const float*)d_in[12];
    float* out = (float*)d_out;

    float *xt, *qraw, *kvg, *wvg, *S1, *S2;
    uint32_t *quh,*qul,*qvh,*qvl,*knh,*knl,*xkh,*xkl,*cbh,*cbl,*xrh,*xrl;
    cudaGetSymbolAddress((void**)&xt,   g_xt);
    cudaGetSymbolAddress((void**)&qraw, g_qraw);
    cudaGetSymbolAddress((void**)&kvg,  g_kvg);
    cudaGetSymbolAddress((void**)&wvg,  g_wvg);
    cudaGetSymbolAddress((void**)&S1,   g_S1);
    cudaGetSymbolAddress((void**)&S2,   g_S2);
    cudaGetSymbolAddress((void**)&quh,  g_quh); cudaGetSymbolAddress((void**)&qul, g_qul);
    cudaGetSymbolAddress((void**)&qvh,  g_qvh); cudaGetSymbolAddress((void**)&qvl, g_qvl);
    cudaGetSymbolAddress((void**)&knh,  g_knh); cudaGetSymbolAddress((void**)&knl, g_knl);
    cudaGetSymbolAddress((void**)&xkh,  g_xkh); cudaGetSymbolAddress((void**)&xkl, g_xkl);
    cudaGetSymbolAddress((void**)&cbh,  g_cbh); cudaGetSymbolAddress((void**)&cbl, g_cbl);
    cudaGetSymbolAddress((void**)&xrh,  g_xrh); cudaGetSymbolAddress((void**)&xrl, g_xrl);

    const int TF32_SMEM = (2*128*36 + 2*32*132) * 4;   // 70656
    cudaFuncSetAttribute(gemm_tf32_kernel,
                         cudaFuncAttributeMaxDynamicSharedMemorySize, TF32_SMEM);
    const int NOSKIP = -(1 << 30);

    // ---- pre-split static inputs + vals assembly ----
    convA_kernel<<<(Hh*Ss*64 + 255)/256, 256>>>(cb,  cbh, cbl, Hh*Ss*64);
    convA_kernel<<<(Hh*WREC*64 + 255)/256, 256>>>(xlr, xrh, xrl, Hh*WREC*64);
    convA_kernel<<<(64*Ll*64 + 255)/256, 256>>>(xlk, xkh, xkl, 64*Ll*64);
    assembleV_kernel<<<8192, 256>>>(xlv, aggU);
    ln_input_kernel<<<Bb*Ll, 256>>>(input);

    // ---- projections ----
    gemm_ffma_kernel<<<dim3(8, 32), 256>>>(xt, Wkvg, kvg, 4096, 3072, 1024);   // k cols fp32
    gemm_tf32_kernel<<<dim3(8, 32), 256, TF32_SMEM>>>(xt, Wq, qraw, 4096, 1024, 1024);
    gemm_tf32_kernel<<<dim3(16, 32), 256, TF32_SMEM>>>(xt, Wkvg + 1024, kvg + 1024,
                                                       4096, 3072, 1024);
    kln_kernel<<<dim3(Bb*Ll, Hh), 128>>>();
    qgate_kernel<<<dim3(Bb*Ll, Hh), 128>>>(xu, xv);
    convV_kernel<<<8192, 256>>>();

    // ---- VQ: bf16 tensor scores + guarded argmin ----
    cc_kernel<<<Hh, Ss>>>(cb);
    gemm_ntbf_kernel<<<dim3(4, 4, 64), 256>>>(
        knh, knl, cbh, cbl, S2,
        (size_t)Ll*64, (size_t)Ss*64, (size_t)Ll*Ss, 1, Ss, 0, NOSKIP);
    argmin_kernel<<<Bb*Hh*Ll/8, 256>>>(cb);

    // ---- attention scores (mask-aware skipping on S2) ----
    gemm_ntbf_kernel<<<dim3(8, 4, 64), 256>>>(          // S2 = qv @ xlr^T
        qvh, qvl, xrh, xrl, S2,
        (size_t)Ll*64, (size_t)WREC*64, (size_t)Ll*WREC, 1, WREC, 0, 384);
    gemm_ntbf_kernel<<<dim3(4, 4, 64), 256>>>(          // S1 xlk cols [0,512)
        quh, qul, xkh, xkl, S1,
        (size_t)Ll*64, (size_t)Ll*64, (size_t)Ll*WTOT, 0, WTOT, 0, NOSKIP);
    gemm_ntbf_kernel<<<dim3(4, 4, 64), 256>>>(          // S1 cb cols [1024,1536)
        quh, qul, cbh, cbl, S1,
        (size_t)Ll*64, (size_t)Ss*64, (size_t)Ll*WTOT, 1, WTOT, 1024, NOSKIP);

    softmax_kernel<<<dim3(Ll, 64), 128>>>(aggL);
    gemm_valbf_kernel<<<dim3(1, Ll/128, 64), 256>>>();
    gemm_tf32_kernel<<<dim3(8, 32), 256, TF32_SMEM>>>(wvg, Wres, out, 4096, 1024, 1024);
}

// round 14
// speedup vs baseline: 1.1648x; 1.0352x over previous
#include <cuda_runtime.h>
#include <cuda_bf16.h>
#include <math.h>
#include <stdint.h>

// Shapes (fixed for this problem)
#define Bb   8
#define Ll   512
#define Mm   512
#define Hh   8
#define DKk  128
#define DVv  128
#define Ss   512
#define DMm  1024
#define WREC 1024
#define WTOT 1536    // recent 1024 + cache 512

#define INVTAU 0.08838834764831845f   // 1/sqrt(128)
#define TAU_GAP 0.01f

// ---------------- scratch (device globals; no allocation allowed) ------------
__device__ float g_xt  [Bb*Ll*DMm];
__device__ float g_qraw[Bb*Ll*Hh*DKk];
__device__ float g_kvg [Bb*Ll*3072];
__device__ float g_kn  [Bb*Hh*Ll*DKk];        // fp32 kn for exact argmin recheck
__device__ float g_g   [Bb*Ll*Hh*DVv];
__device__ float g_vmid[64*Ll*DVv];           // current v (pre-pair scratch)
__device__ float g_S1  [(size_t)64*Ll*WTOT];  // raw scores
__device__ float g_S2  [(size_t)64*Ll*WREC];  // VQ scores scratch, then BD term
__device__ float g_P   [(size_t)64*Ll*WTOT];  // probabilities (fp32), 1536 per row
__device__ float g_wvg [Bb*Ll*Hh*DVv];
__device__ float g_cc  [Hh*Ss];
__device__ int   g_z   [Bb*Hh*Ll];

// pre-split bf16 (hi,lo) pair arrays: pair couples k (or w) elements 2j,2j+1
__device__ uint32_t g_quh[64*Ll*64],  g_qul[64*Ll*64];
__device__ uint32_t g_qvh[64*Ll*64],  g_qvl[64*Ll*64];
__device__ uint32_t g_knh[64*Ll*64],  g_knl[64*Ll*64];
__device__ uint32_t g_xkh[64*Ll*64],  g_xkl[64*Ll*64];   // xl_k_hat
__device__ uint32_t g_cbh[Hh*Ss*64],  g_cbl[Hh*Ss*64];   // codebook
__device__ uint32_t g_xrh[Hh*WREC*64],g_xrl[Hh*WREC*64]; // xl_r
__device__ uint32_t g_vh [(size_t)64*768*128], g_vl [(size_t)64*768*128]; // vals (w-pairs)

// ---------------- helpers ----------------------------------------------------
__device__ __forceinline__ uint32_t tf32_of(float x) {
    uint32_t u;
    asm("cvt.rna.tf32.f32 %0, %1;" : "=r"(u) : "f"(x));
    return u;
}

__device__ __forceinline__ uint32_t smem_u32(const void* p) {
    return (uint32_t)__cvta_generic_to_shared(p);
}
#define CP_ASYNC16(dst, src) \
    asm volatile("cp.async.cg.shared.global [%0], [%1], 16;" :: "r"(dst), "l"(src))
#define CP_COMMIT() asm volatile("cp.async.commit_group;")
#define CP_WAIT1()  asm volatile("cp.async.wait_group 1;")
#define CP_WAIT0()  asm volatile("cp.async.wait_group 0;")

__device__ __forceinline__ void mma_tf32(float* c, const uint32_t* a, const uint32_t* b) {
    asm volatile(
        "mma.sync.aligned.m16n8k8.row.col.f32.tf32.tf32.f32 "
        "{%0,%1,%2,%3}, {%4,%5,%6,%7}, {%8,%9}, {%0,%1,%2,%3};"
        : "+f"(c[0]), "+f"(c[1]), "+f"(c[2]), "+f"(c[3])
        : "r"(a[0]), "r"(a[1]), "r"(a[2]), "r"(a[3]), "r"(b[0]), "r"(b[1]));
}

__device__ __forceinline__ void mma_bf16(float* c, const uint32_t* a, const uint32_t* b) {
    asm volatile(
        "mma.sync.aligned.m16n8k16.row.col.f32.bf16.bf16.f32 "
        "{%0,%1,%2,%3}, {%4,%5,%6,%7}, {%8,%9}, {%0,%1,%2,%3};"
        : "+f"(c[0]), "+f"(c[1]), "+f"(c[2]), "+f"(c[3])
        : "r"(a[0]), "r"(a[1]), "r"(a[2]), "r"(a[3]), "r"(b[0]), "r"(b[1]));
}

// split two floats into packed bf16x2 hi and lo words (pair: x->low, y->high)
__device__ __forceinline__ void split2(float x, float y, uint32_t& hi, uint32_t& lo) {
    __nv_bfloat162 h = __floats2bfloat162_rn(x, y);
    float hx = __bfloat162float(h.x), hy = __bfloat162float(h.y);
    __nv_bfloat162 l = __floats2bfloat162_rn(x - hx, y - hy);
    hi = *(uint32_t*)&h;
    lo = *(uint32_t*)&l;
}

__device__ __forceinline__ float blockReduceSum256(float v, float* sh) {
    #pragma unroll
    for (int o = 16; o > 0; o >>= 1) v += __shfl_xor_sync(0xffffffffu, v, o);
    __syncthreads();
    if ((threadIdx.x & 31) == 0) sh[threadIdx.x >> 5] = v;
    __syncthreads();
    float r = 0.f;
    #pragma unroll
    for (int i = 0; i < 8; i++) r += sh[i];
    return r;
}

__device__ __forceinline__ float blockReduceSum128(float v, float* sh) {
    #pragma unroll
    for (int o = 16; o > 0; o >>= 1) v += __shfl_xor_sync(0xffffffffu, v, o);
    __syncthreads();
    if ((threadIdx.x & 31) == 0) sh[threadIdx.x >> 5] = v;
    __syncthreads();
    return sh[0] + sh[1] + sh[2] + sh[3];
}

// ---------------- 0a) generic pre-split (pairs along contiguous k) -----------
__global__ void convA_kernel(const float* __restrict__ src, uint32_t* __restrict__ dh,
                             uint32_t* __restrict__ dl, int totalPairs) {
    int i = blockIdx.x*256 + threadIdx.x;
    if (i >= totalPairs) return;
    float2 v = *(const float2*)&src[2*i];
    uint32_t hi, lo; split2(v.x, v.y, hi, lo);
    dh[i] = hi; dl[i] = lo;
}

// ---------------- 0b) vals assembly (pairs across w rows) --------------------
__global__ void assembleV_kernel(const float* __restrict__ xlv,
                                 const float* __restrict__ aggU) {
    int idx = blockIdx.x*256 + threadIdx.x;   // 64*256*128 = 2M
    int d = idx & 127; int rest = idx >> 7;
    int ip = rest & 255; int bh = rest >> 8;
    size_t si = ((size_t)bh*512 + 2*ip)*128 + d;
    uint32_t hi, lo;
    split2(xlv[si], xlv[si + 128], hi, lo);
    size_t o = ((size_t)bh*768 + ip)*128 + d;
    g_vh[o] = hi; g_vl[o] = lo;
    split2(aggU[si], aggU[si + 128], hi, lo);
    o = ((size_t)bh*768 + 512 + ip)*128 + d;
    g_vh[o] = hi; g_vl[o] = lo;
}

// current v rows (g_vmid) -> vals pairs 256..511
__global__ void convV_kernel() {
    int idx = blockIdx.x*256 + threadIdx.x;   // 2M
    int d = idx & 127; int rest = idx >> 7;
    int ip = rest & 255; int bh = rest >> 8;
    float a = g_vmid[((size_t)bh*512 + 2*ip)*128 + d];
    float b = g_vmid[((size_t)bh*512 + 2*ip + 1)*128 + d];
    uint32_t hi, lo; split2(a, b, hi, lo);
    size_t o = ((size_t)bh*768 + 256 + ip)*128 + d;
    g_vh[o] = hi; g_vl[o] = lo;
}

// ---------------- 1) LayerNorm of input (rows of 1024) -----------------------
__global__ void ln_input_kernel(const float* __restrict__ x) {
    __shared__ float sh[8];
    size_t base = (size_t)blockIdx.x * DMm;
    float lv[4]; float s = 0.f;
    #pragma unroll
    for (int j = 0; j < 4; j++) { lv[j] = x[base + threadIdx.x + j*256]; s += lv[j]; }
    float mu = blockReduceSum256(s, sh) * (1.f/1024.f);
    float s2 = 0.f;
    #pragma unroll
    for (int j = 0; j < 4; j++) { float d = lv[j] - mu; s2 += d*d; }
    float var = blockReduceSum256(s2, sh) * (1.f/1024.f);
    float rstd = rsqrtf(var + 1e-6f);
    #pragma unroll
    for (int j = 0; j < 4; j++) g_xt[base + threadIdx.x + j*256] = (lv[j]-mu)*rstd;
}

// ---------------- 2a) fp32 FFMA GEMM (full precision, k-columns) -------------
__global__ void __launch_bounds__(256, 2)
gemm_ffma_kernel(const float* __restrict__ A, const float* __restrict__ B,
                 float* __restrict__ C, int M, int N, int K) {
    __shared__ float As[16][132];
    __shared__ float Bs[16][132];
    int tid  = threadIdx.x;
    int row0 = blockIdx.y * 128;
    int col0 = blockIdx.x * 128;
    int tx = tid & 15, ty = tid >> 4;

    float acc[8][8];
    #pragma unroll
    for (int i = 0; i < 8; i++)
        #pragma unroll
        for (int j = 0; j < 8; j++) acc[i][j] = 0.f;

    for (int k0 = 0; k0 < K; k0 += 16) {
        #pragma unroll
        for (int i = 0; i < 2; i++) {
            int f = tid + i*256;
            int r = f >> 2, c4 = f & 3;
            float4 v = *(const float4*)&A[(size_t)(row0 + r)*K + k0 + c4*4];
            As[c4*4+0][r] = v.x; As[c4*4+1][r] = v.y;
            As[c4*4+2][r] = v.z; As[c4*4+3][r] = v.w;
        }
        #pragma unroll
        for (int i = 0; i < 2; i++) {
            int f = tid + i*256;
            int r = f >> 5, c4 = f & 31;
            *(float4*)&Bs[r][c4*4] = *(const float4*)&B[(size_t)(k0 + r)*N + col0 + c4*4];
        }
        __syncthreads();
        #pragma unroll
        for (int kk = 0; kk < 16; kk++) {
            float a[8], bb[8];
            *(float4*)&a[0]  = *(float4*)&As[kk][ty*8];
            *(float4*)&a[4]  = *(float4*)&As[kk][ty*8 + 4];
            *(float4*)&bb[0] = *(float4*)&Bs[kk][tx*4];
            *(float4*)&bb[4] = *(float4*)&Bs[kk][64 + tx*4];
            #pragma unroll
            for (int i = 0; i < 8; i++)
                #pragma unroll
                for (int j = 0; j < 8; j++) acc[i][j] += a[i]*bb[j];
        }
        __syncthreads();
    }
    #pragma unroll
    for (int i = 0; i < 8; i++) {
        size_t crow = (size_t)(row0 + ty*8 + i)*N;
        *(float4*)&C[crow + col0 + tx*4]      = make_float4(acc[i][0], acc[i][1], acc[i][2], acc[i][3]);
        *(float4*)&C[crow + col0 + 64 + tx*4] = make_float4(acc[i][4], acc[i][5], acc[i][6], acc[i][7]);
    }
}

// ---------------- 2b) tf32 1-term GEMM, cp.async double-buffered -------------
__global__ void __launch_bounds__(256, 2)
gemm_tf32_kernel(const float* __restrict__ A, const float* __restrict__ B,
                 float* __restrict__ C, int M, int N, int K) {
    extern __shared__ float sm[];
    const int ASZ = 128*36, BSZ = 32*132;
    int tid  = threadIdx.x;
    int warp = tid >> 5, lane = tid & 31;
    int g  = lane >> 2, tg = lane & 3;
    int wm = (warp >> 1) * 32;
    int wn = (warp & 1) * 64;
    int row0 = blockIdx.y * 128;
    int col0 = blockIdx.x * 128;

    float c[2][8][4];
    #pragma unroll
    for (int mt = 0; mt < 2; mt++)
        #pragma unroll
        for (int nt = 0; nt < 8; nt++)
            #pragma unroll
            for (int j = 0; j < 4; j++) c[mt][nt][j] = 0.f;

    #define STAGE(k0_, buf_) do {                                              \
        float* As_ = sm + (buf_)*ASZ;                                          \
        float* Bs_ = sm + 2*ASZ + (buf_)*BSZ;                                  \
        _Pragma("unroll")                                                      \
        for (int i_ = 0; i_ < 4; i_++) {                                       \
            int f_ = tid + i_*256;                                             \
            int r_ = f_ >> 3, c4_ = (f_ & 7) * 4;                              \
            CP_ASYNC16(smem_u32(&As_[r_*36 + c4_]),                            \
                       &A[(size_t)(row0 + r_)*K + (k0_) + c4_]);               \
        }                                                                      \
        _Pragma("unroll")                                                      \
        for (int i_ = 0; i_ < 4; i_++) {                                       \
            int f_ = tid + i_*256;                                             \
            int r_ = f_ >> 5, c4_ = (f_ & 31) * 4;                             \
            CP_ASYNC16(smem_u32(&Bs_[r_*132 + c4_]),                           \
                       &B[(size_t)((k0_) + r_)*N + col0 + c4_]);               \
        }                                                                      \
    } while (0)

    STAGE(0, 0); CP_COMMIT();

    for (int k0 = 0; k0 < K; k0 += 32) {
        int buf = (k0 >> 5) & 1;
        if (k0 + 32 < K) { STAGE(k0 + 32, buf ^ 1); CP_COMMIT(); CP_WAIT1(); }
        else             { CP_WAIT0(); }
        __syncthreads();
        float* As = sm + buf*ASZ;
        float* Bs = sm + 2*ASZ + buf*BSZ;
        #pragma unroll
        for (int ks = 0; ks < 4; ks++) {
            int kk = ks * 8;
            uint32_t a[2][4], b[8][2];
            #pragma unroll
            for (int mt = 0; mt < 2; mt++) {
                int m0 = wm + mt*16;
                a[mt][0] = tf32_of(As[(m0 + g    )*36 + kk + tg    ]);
                a[mt][1] = tf32_of(As[(m0 + g + 8)*36 + kk + tg    ]);
                a[mt][2] = tf32_of(As[(m0 + g    )*36 + kk + tg + 4]);
                a[mt][3] = tf32_of(As[(m0 + g + 8)*36 + kk + tg + 4]);
            }
            #pragma unroll
            for (int nt = 0; nt < 8; nt++) {
                int n0 = wn + nt*8 + g;
                b[nt][0] = tf32_of(Bs[(kk + tg    )*132 + n0]);
                b[nt][1] = tf32_of(Bs[(kk + tg + 4)*132 + n0]);
            }
            #pragma unroll
            for (int mt = 0; mt < 2; mt++)
                #pragma unroll
                for (int nt = 0; nt < 8; nt++)
                    mma_tf32(c[mt][nt], a[mt], b[nt]);
        }
        __syncthreads();
    }
    #undef STAGE

    #pragma unroll
    for (int mt = 0; mt < 2; mt++) {
        int row = row0 + wm + mt*16 + g;
        #pragma unroll
        for (int nt = 0; nt < 8; nt++) {
            int col = col0 + wn + nt*8 + tg*2;
            *(float2*)&C[(size_t)row*N + col]     = make_float2(c[mt][nt][0], c[mt][nt][1]);
            *(float2*)&C[(size_t)(row+8)*N + col] = make_float2(c[mt][nt][2], c[mt][nt][3]);
        }
    }
}

// ---------------- 2c) batched NT bf16 3-term GEMM, cp.async pipelined --------
// Pre-split operands; dynamic smem 2 stages x 4 arrays x [128][20] u32.
__global__ void __launch_bounds__(256, 2)
gemm_ntbf_kernel(const uint32_t* __restrict__ Ahg, const uint32_t* __restrict__ Alg,
                 const uint32_t* __restrict__ Bhg, const uint32_t* __restrict__ Blg,
                 float* __restrict__ C,
                 size_t strideA, size_t strideB, size_t strideC,
                 int bPerHead, int ldC, int colOff, int skipThresh) {
    extern __shared__ uint32_t smu[];
    const int STG = 10240;   // 4 * 2560 u32 per stage

    int row0 = blockIdx.y * 128;
    int col0 = blockIdx.x * 128;
    if (col0 + 128 <= skipThresh - row0) return;   // masked-out S2 tiles

    int z = blockIdx.z;
    const uint32_t* Azh = Ahg + (size_t)z * strideA;
    const uint32_t* Azl = Alg + (size_t)z * strideA;
    size_t bo = (size_t)(bPerHead ? (z & 7) : z) * strideB;
    const uint32_t* Bzh = Bhg + bo;
    const uint32_t* Bzl = Blg + bo;
    float* Cz = C + (size_t)z * strideC;

    int tid  = threadIdx.x;
    int warp = tid >> 5, lane = tid & 31;
    int g  = lane >> 2, tg = lane & 3;
    int wm = (warp >> 1) * 32;
    int wn = (warp & 1) * 64;

    float c[2][8][4];
    #pragma unroll
    for (int mt = 0; mt < 2; mt++)
        #pragma unroll
        for (int nt = 0; nt < 8; nt++)
            #pragma unroll
            for (int j = 0; j < 4; j++) c[mt][nt][j] = 0.f;

    #define NTSTAGE(kp0_, buf_) do {                                           \
        uint32_t* AH_ = smu + (buf_)*STG;                                      \
        uint32_t* AL_ = AH_ + 2560;                                            \
        uint32_t* BH_ = AH_ + 5120;                                            \
        uint32_t* BL_ = AH_ + 7680;                                            \
        _Pragma("unroll")                                                      \
        for (int i_ = 0; i_ < 2; i_++) {                                       \
            int f_ = tid + i_*256;                                             \
            int r_ = f_ >> 2, q4_ = (f_ & 3) * 4;                              \
            CP_ASYNC16(smem_u32(&AH_[r_*20 + q4_]),                            \
                       &Azh[(size_t)(row0 + r_)*64 + (kp0_) + q4_]);           \
            CP_ASYNC16(smem_u32(&AL_[r_*20 + q4_]),                            \
                       &Azl[(size_t)(row0 + r_)*64 + (kp0_) + q4_]);           \
            CP_ASYNC16(smem_u32(&BH_[r_*20 + q4_]),                            \
                       &Bzh[(size_t)(col0 + r_)*64 + (kp0_) + q4_]);           \
            CP_ASYNC16(smem_u32(&BL_[r_*20 + q4_]),                            \
                       &Bzl[(size_t)(col0 + r_)*64 + (kp0_) + q4_]);           \
        }                                                                      \
    } while (0)

    NTSTAGE(0, 0); CP_COMMIT();

    for (int ch = 0; ch < 4; ch++) {
        int buf = ch & 1;
        if (ch < 3) { NTSTAGE((ch + 1)*16, buf ^ 1); CP_COMMIT(); CP_WAIT1(); }
        else        { CP_WAIT0(); }
        __syncthreads();
        const uint32_t* AH = smu + buf*STG;
        const uint32_t* AL = AH + 2560;
        const uint32_t* BH = AH + 5120;
        const uint32_t* BL = AH + 7680;
        #pragma unroll
        for (int c16 = 0; c16 < 2; c16++) {
            int coff = c16 * 8;
            uint32_t ah[2][4], al[2][4];
            #pragma unroll
            for (int mt = 0; mt < 2; mt++) {
                int m0 = wm + mt*16;
                ah[mt][0] = AH[(m0 + g    )*20 + coff + tg    ];
                ah[mt][1] = AH[(m0 + g + 8)*20 + coff + tg    ];
                ah[mt][2] = AH[(m0 + g    )*20 + coff + tg + 4];
                ah[mt][3] = AH[(m0 + g + 8)*20 + coff + tg + 4];
                al[mt][0] = AL[(m0 + g    )*20 + coff + tg    ];
                al[mt][1] = AL[(m0 + g + 8)*20 + coff + tg    ];
                al[mt][2] = AL[(m0 + g    )*20 + coff + tg + 4];
                al[mt][3] = AL[(m0 + g + 8)*20 + coff + tg + 4];
            }
            #pragma unroll
            for (int nt = 0; nt < 8; nt++) {
                int n0 = wn + nt*8 + g;
                uint32_t bh[2], bl[2];
                bh[0] = BH[n0*20 + coff + tg    ];
                bh[1] = BH[n0*20 + coff + tg + 4];
                bl[0] = BL[n0*20 + coff + tg    ];
                bl[1] = BL[n0*20 + coff + tg + 4];
                #pragma unroll
                for (int mt = 0; mt < 2; mt++) {
                    mma_bf16(c[mt][nt], ah[mt], bh);
                    mma_bf16(c[mt][nt], ah[mt], bl);
                    mma_bf16(c[mt][nt], al[mt], bh);
                }
            }
        }
        __syncthreads();
    }
    #undef NTSTAGE

    #pragma unroll
    for (int mt = 0; mt < 2; mt++) {
        int row = row0 + wm + mt*16 + g;
        #pragma unroll
        for (int nt = 0; nt < 8; nt++) {
            int col = colOff + col0 + wn + nt*8 + tg*2;
            *(float2*)&Cz[(size_t)row*ldC + col]     = make_float2(c[mt][nt][0], c[mt][nt][1]);
            *(float2*)&Cz[(size_t)(row+8)*ldC + col] = make_float2(c[mt][nt][2], c[mt][nt][3]);
        }
    }
}

// ---------------- 2d) value GEMM: P fp32 (split on load) x pre-split vals ----
__global__ void __launch_bounds__(256, 2)
gemm_valbf_kernel() {
    __shared__ uint32_t Ah[128][20], Al[128][20];
    __shared__ uint32_t BhT[16][136], BlT[16][136];

    int z = blockIdx.z;
    int b = z >> 3, h = z & 7;
    const float*    Pz  = g_P  + (size_t)z * Ll * WTOT;
    const uint32_t* Bzh = g_vh + (size_t)z * 768 * 128;
    const uint32_t* Bzl = g_vl + (size_t)z * 768 * 128;

    int tid  = threadIdx.x;
    int warp = tid >> 5, lane = tid & 31;
    int g  = lane >> 2, tg = lane & 3;
    int wm = (warp >> 1) * 32;
    int wn = (warp & 1) * 64;
    int row0 = blockIdx.y * 128;

    float c[2][8][4];
    #pragma unroll
    for (int mt = 0; mt < 2; mt++)
        #pragma unroll
        for (int nt = 0; nt < 8; nt++)
            #pragma unroll
            for (int j = 0; j < 4; j++) c[mt][nt][j] = 0.f;

    for (int kp0 = 0; kp0 < 768; kp0 += 16) {
        int k0 = kp0 * 2;
        if (k0 >= row0 + 640 && k0 + 32 <= 1024) continue;   // causal-masked zero block
        #pragma unroll
        for (int i = 0; i < 2; i++) {
            int f = tid + i*256;
            int r = f >> 2, qp = (f & 3) * 4;
            const float* src = Pz + (size_t)(row0 + r)*WTOT + (kp0 + qp)*2;
            float4 v0 = *(const float4*)&src[0];
            float4 v1 = *(const float4*)&src[4];
            uint32_t h0,l0,h1,l1,h2,l2,h3,l3;
            split2(v0.x, v0.y, h0, l0);
            split2(v0.z, v0.w, h1, l1);
            split2(v1.x, v1.y, h2, l2);
            split2(v1.z, v1.w, h3, l3);
            *(uint4*)&Ah[r][qp] = make_uint4(h0, h1, h2, h3);
            *(uint4*)&Al[r][qp] = make_uint4(l0, l1, l2, l3);
        }
        #pragma unroll
        for (int i = 0; i < 2; i++) {
            int f = tid + i*256;
            int kp = f >> 5, n4 = (f & 31) * 4;
            *(uint4*)&BhT[kp][n4] = *(const uint4*)&Bzh[(size_t)(kp0 + kp)*128 + n4];
            *(uint4*)&BlT[kp][n4] = *(const uint4*)&Bzl[(size_t)(kp0 + kp)*128 + n4];
        }
        __syncthreads();
        #pragma unroll
        for (int c16 = 0; c16 < 2; c16++) {
            int coff = c16 * 8;
            uint32_t ah[2][4], al[2][4];
            #pragma unroll
            for (int mt = 0; mt < 2; mt++) {
                int m0 = wm + mt*16;
                ah[mt][0] = Ah[m0 + g    ][coff + tg    ];
                ah[mt][1] = Ah[m0 + g + 8][coff + tg    ];
                ah[mt][2] = Ah[m0 + g    ][coff + tg + 4];
                ah[mt][3] = Ah[m0 + g + 8][coff + tg + 4];
                al[mt][0] = Al[m0 + g    ][coff + tg    ];
                al[mt][1] = Al[m0 + g + 8][coff + tg    ];
                al[mt][2] = Al[m0 + g    ][coff + tg + 4];
                al[mt][3] = Al[m0 + g + 8][coff + tg + 4];
            }
            #pragma unroll
            for (int nt = 0; nt < 8; nt++) {
                int n0 = wn + nt*8 + g;
                uint32_t bh[2], bl[2];
                bh[0] = BhT[coff + tg    ][n0];
                bh[1] = BhT[coff + tg + 4][n0];
                bl[0] = BlT[coff + tg    ][n0];
                bl[1] = BlT[coff + tg + 4][n0];
                #pragma unroll
                for (int mt = 0; mt < 2; mt++) {
                    mma_bf16(c[mt][nt], ah[mt], bh);
                    mma_bf16(c[mt][nt], ah[mt], bl);
                    mma_bf16(c[mt][nt], al[mt], bh);
                }
            }
        }
        __syncthreads();
    }

    #pragma unroll
    for (int mt = 0; mt < 2; mt++) {
        int row = row0 + wm + mt*16 + g;
        #pragma unroll
        for (int nt = 0; nt < 8; nt++) {
            int col = wn + nt*8 + tg*2;
            size_t o0 = ((size_t)(b*Ll + row))*1024 + h*128 + col;
            size_t o1 = ((size_t)(b*Ll + row + 8))*1024 + h*128 + col;
            float2 g0 = *(const float2*)&g_g[o0];
            float2 g1 = *(const float2*)&g_g[o1];
            *(float2*)&g_wvg[o0] = make_float2(c[mt][nt][0]*g0.x, c[mt][nt][1]*g0.y);
            *(float2*)&g_wvg[o1] = make_float2(c[mt][nt][2]*g1.x, c[mt][nt][3]*g1.y);
        }
    }
}

// ---------------- 3a) k LN + pre-split kn ------------------------------------
__global__ void kln_kernel() {
    __shared__ float sh[4];
    int bl = blockIdx.x, h = blockIdx.y, t = threadIdx.x;
    int b = bl >> 9, l = bl & 511;
    size_t bh = (size_t)(b*Hh + h);

    float x  = g_kvg[(size_t)bl*3072 + h*128 + t];
    float mu = blockReduceSum128(x, sh) * (1.f/128.f);
    float d  = x - mu;
    float var = blockReduceSum128(d*d, sh) * (1.f/128.f);
    float kn = d * rsqrtf(var + 1e-6f);
    g_kn[(bh*Ll + l)*128 + t] = kn;

    float knp = __shfl_down_sync(0xffffffffu, kn, 1);
    if ((t & 1) == 0) {
        uint32_t hi, lo; split2(kn, knp, hi, lo);
        size_t o = (bh*Ll + l)*64 + (t >> 1);
        g_knh[o] = hi; g_knl[o] = lo;
    }
}

// ---------------- 3b) q LN + qu/qv pre-split, v copy, gate -------------------
__global__ void qgate_kernel(const float* __restrict__ xu, const float* __restrict__ xv) {
    __shared__ float sh[4];
    int bl = blockIdx.x, h = blockIdx.y, t = threadIdx.x;
    int b = bl >> 9, l = bl & 511;
    size_t bh = (size_t)(b*Hh + h);

    float x  = g_qraw[(size_t)bl*1024 + h*128 + t];
    float mu = blockReduceSum128(x, sh) * (1.f/128.f);
    float d  = x - mu;
    float var = blockReduceSum128(d*d, sh) * (1.f/128.f);
    float qn = d * rsqrtf(var + 1e-6f);
    float quv = qn + xu[h*128 + t];
    float qvv = qn + xv[h*128 + t];

    float qup = __shfl_down_sync(0xffffffffu, quv, 1);
    float qvp = __shfl_down_sync(0xffffffffu, qvv, 1);
    if ((t & 1) == 0) {
        size_t o = (bh*Ll + l)*64 + (t >> 1);
        uint32_t hi, lo;
        split2(quv, qup, hi, lo); g_quh[o] = hi; g_qul[o] = lo;
        split2(qvv, qvp, hi, lo); g_qvh[o] = hi; g_qvl[o] = lo;
    }

    g_vmid[(bh*Ll + l)*128 + t] = g_kvg[(size_t)bl*3072 + 1024 + h*128 + t];

    float gx = g_kvg[(size_t)bl*3072 + 2048 + h*128 + t];
    g_g[(size_t)bl*1024 + h*128 + t] = gx / (1.f + __expf(-gx));
}

// ---------------- 4a) codebook squared norms ---------------------------------
__global__ void cc_kernel(const float* __restrict__ codebook) {
    int h = blockIdx.x, s = threadIdx.x;
    const float4* c = (const float4*)(codebook + ((size_t)h*Ss + s)*128);
    float acc = 0.f;
    #pragma unroll 8
    for (int i = 0; i < 32; i++) {
        float4 v = c[i];
        acc += v.x*v.x + v.y*v.y + v.z*v.z + v.w*v.w;
    }
    g_cc[h*Ss + s] = acc;
}

// ---------------- 4b) guarded argmin: approx best/2nd, exact recheck ---------
__global__ void argmin_kernel(const float* __restrict__ codebook) {
    int t = blockIdx.x * 8 + (threadIdx.x >> 5);
    int lane = threadIdx.x & 31;
    int z = t >> 9;
    int h = z & 7;
    const float* sc = g_S2 + (size_t)t * 512;
    const float* cc = g_cc + h*512;

    float b1 = 3.4e38f, b2 = 3.4e38f; int i1 = 0x7fffffff;
    for (int s = lane; s < 512; s += 32) {
        float v = cc[s] - 2.f*sc[s];
        if (v < b1) { b2 = b1; b1 = v; i1 = s; }
        else if (v < b2) b2 = v;
    }
    #pragma unroll
    for (int o = 16; o > 0; o >>= 1) {
        float ov1 = __shfl_xor_sync(0xffffffffu, b1, o);
        int   oi1 = __shfl_xor_sync(0xffffffffu, i1, o);
        float ov2 = __shfl_xor_sync(0xffffffffu, b2, o);
        if (ov1 < b1 || (ov1 == b1 && oi1 < i1)) {
            b2 = fminf(b1, ov2);
            b1 = ov1; i1 = oi1;
        } else {
            b2 = fminf(b2, ov1);
        }
    }
    if (b2 - b1 < TAU_GAP) {
        const float* kr = g_kn + (size_t)t * 128;
        float be = 3.4e38f; int ie = 0x7fffffff;
        for (int s = lane; s < 512; s += 32) {
            const float4* c = (const float4*)(codebook + ((size_t)h*Ss + s)*128);
            float dot = 0.f, ccv = 0.f;
            #pragma unroll 4
            for (int d4 = 0; d4 < 32; d4++) {
                float4 cv = c[d4];
                float4 kv = *(const float4*)&kr[d4*4];
                ccv += cv.x*cv.x + cv.y*cv.y + cv.z*cv.z + cv.w*cv.w;
                dot += cv.x*kv.x + cv.y*kv.y + cv.z*kv.z + cv.w*kv.w;
            }
            float v = ccv - 2.f*dot;
            if (v < be) { be = v; ie = s; }
        }
        #pragma unroll
        for (int o = 16; o > 0; o >>= 1) {
            float ov = __shfl_xor_sync(0xffffffffu, be, o);
            int   oi = __shfl_xor_sync(0xffffffffu, ie, o);
            if (ov < be || (ov == be && oi < ie)) { be = ov; ie = oi; }
        }
        i1 = ie;
    }
    if (lane == 0) g_z[t] = i1;
}

// ---------------- 6) softmax with fused c_z gather; emits fp32 probs ---------
__global__ void softmax_kernel(const float* __restrict__ aggL) {
    __shared__ float red[4];
    int l = blockIdx.x, z = blockIdx.y, tid = threadIdx.x;
    const float* S1row = g_S1 + ((size_t)z*Ll + l)*WTOT;
    const float* S2row = g_S2 + ((size_t)z*Ll + l)*WREC;
    const int* zrow = g_z + (size_t)z*Ll;
    int limit = l + Mm;

    float pv[12];
    float m = -3.4e38f;
    #pragma unroll
    for (int i = 0; i < 6; i++) {
        int p = tid + i*128;
        #pragma unroll
        for (int u = 0; u < 2; u++) {
            int w = 2*p + u;
            float s;
            if (w < 512) {
                s = (S1row[w] + S2row[w + 511 - l]) * INVTAU;
            } else if (w < WREC) {
                if (w <= limit)
                    s = (S1row[1024 + zrow[w - 512]] + S2row[w + 511 - l]) * INVTAU;
                else
                    s = -3.4e38f;
            } else {
                float al = aggL[(size_t)z*Ss + (w - WREC)];
                float bias = (al > 0.f) ? logf(fmaxf(al, 1e-30f)) : -1e30f;
                s = S1row[w] * INVTAU + bias;
            }
            pv[2*i+u] = s;
            m = fmaxf(m, s);
        }
    }
    #pragma unroll
    for (int o = 16; o > 0; o >>= 1) m = fmaxf(m, __shfl_xor_sync(0xffffffffu, m, o));
    if ((tid & 31) == 0) red[tid >> 5] = m;
    __syncthreads();
    m = fmaxf(fmaxf(red[0], red[1]), fmaxf(red[2], red[3]));
    __syncthreads();

    float ssum = 0.f;
    #pragma unroll
    for (int i = 0; i < 12; i++) {
        float p = (pv[i] > -1e37f) ? __expf(pv[i] - m) : 0.f;
        pv[i] = p;
        ssum += p;
    }
    #pragma unroll
    for (int o = 16; o > 0; o >>= 1) ssum += __shfl_xor_sync(0xffffffffu, ssum, o);
    if ((tid & 31) == 0) red[tid >> 5] = ssum;
    __syncthreads();
    float invd = 1.f / (red[0] + red[1] + red[2] + red[3]);

    float* Prow = g_P + ((size_t)z*Ll + l)*WTOT;
    #pragma unroll
    for (int i = 0; i < 6; i++) {
        int p = tid + i*128;
        *(float2*)&Prow[2*p] = make_float2(pv[2*i]*invd, pv[2*i+1]*invd);
    }
}

// ---------------- launch ------------------------------------------------------
extern "C" void kernel_launch(void* const* d_in, const int* in_sizes, int n_in,
                              void* d_out, int out_size) {
    const float* input = (const float*)d_in[0];
    const float* xlk   = (const float*)d_in[2];
    const float* xlv   = (const float*)d_in[3];
    const float* aggU  = (const float*)d_in[4];
    const float* aggL  = (const float*)d_in[5];
    const float* Wq    = (const float*)d_in[6];
    const float* Wkvg  = (const float*)d_in[7];
    const float* Wres  = (const float*)d_in[8];
    const float* xu    = (const float*)d_in[9];
    const float* xv    = (const float*)d_in[10];
    const float* xlr   = (const float*)d_in[11];
    const float* cb    = (const float*)d_in[12];
    float* out = (float*)d_out;

    float *xt, *qraw, *kvg, *wvg, *S1, *S2;
    uint32_t *quh,*qul,*qvh,*qvl,*knh,*knl,*xkh,*xkl,*cbh,*cbl,*xrh,*xrl;
    cudaGetSymbolAddress((void**)&xt,   g_xt);
    cudaGetSymbolAddress((void**)&qraw, g_qraw);
    cudaGetSymbolAddress((void**)&kvg,  g_kvg);
    cudaGetSymbolAddress((void**)&wvg,  g_wvg);
    cudaGetSymbolAddress((void**)&S1,   g_S1);
    cudaGetSymbolAddress((void**)&S2,   g_S2);
    cudaGetSymbolAddress((void**)&quh,  g_quh); cudaGetSymbolAddress((void**)&qul, g_qul);
    cudaGetSymbolAddress((void**)&qvh,  g_qvh); cudaGetSymbolAddress((void**)&qvl, g_qvl);
    cudaGetSymbolAddress((void**)&knh,  g_knh); cudaGetSymbolAddress((void**)&knl, g_knl);
    cudaGetSymbolAddress((void**)&xkh,  g_xkh); cudaGetSymbolAddress((void**)&xkl, g_xkl);
    cudaGetSymbolAddress((void**)&cbh,  g_cbh); cudaGetSymbolAddress((void**)&cbl, g_cbl);
    cudaGetSymbolAddress((void**)&xrh,  g_xrh); cudaGetSymbolAddress((void**)&xrl, g_xrl);

    const int TF32_SMEM = (2*128*36 + 2*32*132) * 4;   // 70656
    const int NTBF_SMEM = 2 * 10240 * 4;               // 81920
    cudaFuncSetAttribute(gemm_tf32_kernel,
                         cudaFuncAttributeMaxDynamicSharedMemorySize, TF32_SMEM);
    cudaFuncSetAttribute(gemm_ntbf_kernel,
                         cudaFuncAttributeMaxDynamicSharedMemorySize, NTBF_SMEM);
    const int NOSKIP = -(1 << 30);

    // ---- pre-split static inputs + vals assembly ----
    convA_kernel<<<(Hh*Ss*64 + 255)/256, 256>>>(cb,  cbh, cbl, Hh*Ss*64);
    convA_kernel<<<(Hh*WREC*64 + 255)/256, 256>>>(xlr, xrh, xrl, Hh*WREC*64);
    convA_kernel<<<(64*Ll*64 + 255)/256, 256>>>(xlk, xkh, xkl, 64*Ll*64);
    assembleV_kernel<<<8192, 256>>>(xlv, aggU);
    ln_input_kernel<<<Bb*Ll, 256>>>(input);

    // ---- projections ----
    gemm_ffma_kernel<<<dim3(8, 32), 256>>>(xt, Wkvg, kvg, 4096, 3072, 1024);   // k cols fp32
    gemm_tf32_kernel<<<dim3(8, 32), 256, TF32_SMEM>>>(xt, Wq, qraw, 4096, 1024, 1024);
    gemm_tf32_kernel<<<dim3(16, 32), 256, TF32_SMEM>>>(xt, Wkvg + 1024, kvg + 1024,
                                                       4096, 3072, 1024);
    kln_kernel<<<dim3(Bb*Ll, Hh), 128>>>();
    qgate_kernel<<<dim3(Bb*Ll, Hh), 128>>>(xu, xv);
    convV_kernel<<<8192, 256>>>();

    // ---- VQ: bf16 tensor scores + guarded argmin ----
    cc_kernel<<<Hh, Ss>>>(cb);
    gemm_ntbf_kernel<<<dim3(4, 4, 64), 256, NTBF_SMEM>>>(
        knh, knl, cbh, cbl, S2,
        (size_t)Ll*64, (size_t)Ss*64, (size_t)Ll*Ss, 1, Ss, 0, NOSKIP);
    argmin_kernel<<<Bb*Hh*Ll/8, 256>>>(cb);

    // ---- attention scores (mask-aware skipping on S2) ----
    gemm_ntbf_kernel<<<dim3(8, 4, 64), 256, NTBF_SMEM>>>(   // S2 = qv @ xlr^T
        qvh, qvl, xrh, xrl, S2,
        (size_t)Ll*64, (size_t)WREC*64, (size_t)Ll*WREC, 1, WREC, 0, 384);
    gemm_ntbf_kernel<<<dim3(4, 4, 64), 256, NTBF_SMEM>>>(   // S1 xlk cols [0,512)
        quh, qul, xkh, xkl, S1,
        (size_t)Ll*64, (size_t)Ll*64, (size_t)Ll*WTOT, 0, WTOT, 0, NOSKIP);
    gemm_ntbf_kernel<<<dim3(4, 4, 64), 256, NTBF_SMEM>>>(   // S1 cb cols [1024,1536)
        quh, qul, cbh, cbl, S1,
        (size_t)Ll*64, (size_t)Ss*64, (size_t)Ll*WTOT, 1, WTOT, 1024, NOSKIP);

    softmax_kernel<<<dim3(Ll, 64), 128>>>(aggL);
    gemm_valbf_kernel<<<dim3(1, Ll/128, 64), 256>>>();
    gemm_tf32_kernel<<<dim3(8, 32), 256, TF32_SMEM>>>(wvg, Wres, out, 4096, 1024, 1024);
}